// round 1
// baseline (speedup 1.0000x reference)
#include <cuda_runtime.h>
#include <math.h>

#define BATCH 16
#define SEQL  1024
#define DM    256
#define DI    512
#define DS    16
#define DR    16
#define NL    4

// ---------------- scratch (static device globals; no allocation) ----------------
__device__ float g_seq  [BATCH*SEQL*DM];      // residual stream
__device__ float g_xn   [BATCH*SEQL*DM];      // rmsnorm output
__device__ float g_xr   [BATCH*SEQL*2*DI];    // in_proj output (xs | res)
__device__ float g_u    [BATCH*SEQL*DI];      // conv+silu output
__device__ float g_dbc  [BATCH*SEQL*64];      // x_proj output (dt:0..15, B:16..31, C:32..47, pad)
__device__ float g_delta[BATCH*SEQL*DI];      // softplus(dt_proj)
__device__ float g_du   [BATCH*SEQL*DI];      // delta*u
__device__ float g_y    [BATCH*SEQL*DI];      // scan output (fused epilogue)
__device__ float g_xpw  [NL*DI*64];           // zero-padded x_proj_w
__device__ float g_part [BATCH*16*DM];        // mean partials

// ---------------- patch extract + LN(48) + embed(48->256) + LN(256) ----------------
__global__ void patch_embed_kernel(const float* __restrict__ x,
                                   const float* __restrict__ plg, const float* __restrict__ plb,
                                   const float* __restrict__ ew,  const float* __restrict__ eb,
                                   const float* __restrict__ elg, const float* __restrict__ elb,
                                   float* __restrict__ seq)
{
    __shared__ float sp[8][48];
    int warp = threadIdx.x >> 5, lane = threadIdx.x & 31;
    int t = blockIdx.x * 8 + warp;          // token id 0..16383
    int b = t >> 10, pos = t & 1023;
    int hy = pos >> 5, wx = pos & 31;

    float p1, p2 = 0.f;
    {
        int j = lane;
        int c = j >> 4, py = (j >> 2) & 3, px = j & 3;
        p1 = x[((b*3 + c)*128 + hy*4 + py)*128 + wx*4 + px];
        if (lane < 16) {
            j = 32 + lane;
            c = j >> 4; py = (j >> 2) & 3; px = j & 3;
            p2 = x[((b*3 + c)*128 + hy*4 + py)*128 + wx*4 + px];
        }
    }
    float s = p1 + p2, ss = p1*p1 + p2*p2;
    #pragma unroll
    for (int o = 16; o > 0; o >>= 1) {
        s  += __shfl_xor_sync(0xffffffffu, s,  o);
        ss += __shfl_xor_sync(0xffffffffu, ss, o);
    }
    float mu  = s * (1.f/48.f);
    float var = ss * (1.f/48.f) - mu*mu;
    float rs  = rsqrtf(var + 1e-5f);
    sp[warp][lane] = (p1 - mu)*rs*plg[lane] + plb[lane];
    if (lane < 16) sp[warp][32+lane] = (p2 - mu)*rs*plg[32+lane] + plb[32+lane];
    __syncwarp();

    float acc[8];
    #pragma unroll
    for (int i = 0; i < 8; i++) acc[i] = eb[lane + 32*i];
    #pragma unroll 4
    for (int j = 0; j < 48; j++) {
        float v = sp[warp][j];
        const float* w = ew + j*DM + lane;
        #pragma unroll
        for (int i = 0; i < 8; i++) acc[i] += v * w[32*i];
    }
    float s2 = 0.f, ss2 = 0.f;
    #pragma unroll
    for (int i = 0; i < 8; i++) { s2 += acc[i]; ss2 += acc[i]*acc[i]; }
    #pragma unroll
    for (int o = 16; o > 0; o >>= 1) {
        s2  += __shfl_xor_sync(0xffffffffu, s2,  o);
        ss2 += __shfl_xor_sync(0xffffffffu, ss2, o);
    }
    float mu2  = s2 * (1.f/256.f);
    float var2 = ss2 * (1.f/256.f) - mu2*mu2;
    float rs2  = rsqrtf(var2 + 1e-5f);
    #pragma unroll
    for (int i = 0; i < 8; i++) {
        int e = lane + 32*i;
        seq[(size_t)t*DM + e] = (acc[i] - mu2)*rs2*elg[e] + elb[e];
    }
}

// ---------------- rmsnorm over DM=256 (warp per token) ----------------
__global__ void rmsnorm_kernel(const float* __restrict__ in, const float* __restrict__ w,
                               float* __restrict__ out)
{
    int warp = threadIdx.x >> 5, lane = threadIdx.x & 31;
    int t = blockIdx.x * 8 + warp;
    const float4* ip = (const float4*)(in + (size_t)t*DM);
    float4 v0 = ip[lane], v1 = ip[lane+32];
    float ss = v0.x*v0.x+v0.y*v0.y+v0.z*v0.z+v0.w*v0.w
             + v1.x*v1.x+v1.y*v1.y+v1.z*v1.z+v1.w*v1.w;
    #pragma unroll
    for (int o = 16; o > 0; o >>= 1) ss += __shfl_xor_sync(0xffffffffu, ss, o);
    float sc = rsqrtf(ss*(1.f/256.f) + 1e-5f);
    const float4* wp = (const float4*)w;
    float4 w0 = wp[lane], w1 = wp[lane+32];
    float4 o0 = make_float4(v0.x*sc*w0.x, v0.y*sc*w0.y, v0.z*sc*w0.z, v0.w*sc*w0.w);
    float4 o1 = make_float4(v1.x*sc*w1.x, v1.y*sc*w1.y, v1.z*sc*w1.z, v1.w*sc*w1.w);
    float4* op = (float4*)(out + (size_t)t*DM);
    op[lane] = o0; op[lane+32] = o1;
}

// ---------------- generic fp32 GEMM: C[M,N] = A[M,K] @ B[K,N] (+C if RESID) ----------------
template<int BM, int BN, int BK, int TM, int TN, bool RESID>
__global__ void __launch_bounds__((BM/TM)*(BN/TN))
gemm_kernel(const float* __restrict__ A, const float* __restrict__ Bm,
            float* __restrict__ C, int M, int N, int K)
{
    constexpr int THREADS = (BM/TM)*(BN/TN);
    __shared__ float As[BK][BM+4];
    __shared__ float Bs[BK][BN];
    const int tid = threadIdx.x;
    const int m0 = blockIdx.y * BM;
    const int n0 = blockIdx.x * BN;
    const int tRow = tid / (BN/TN);
    const int tCol = tid % (BN/TN);

    float acc[TM][TN];
    #pragma unroll
    for (int i = 0; i < TM; i++)
        #pragma unroll
        for (int j = 0; j < TN; j++) acc[i][j] = 0.f;

    constexpr int AITER = (BM*BK/4) / THREADS;
    constexpr int BITER = (BK*BN/4) / THREADS;

    for (int k0 = 0; k0 < K; k0 += BK) {
        #pragma unroll
        for (int it = 0; it < AITER; it++) {
            int v   = tid + it*THREADS;
            int row = v / (BK/4);
            int cv  = v % (BK/4);
            float4 a = *(const float4*)(A + (size_t)(m0+row)*K + k0 + cv*4);
            As[cv*4+0][row] = a.x; As[cv*4+1][row] = a.y;
            As[cv*4+2][row] = a.z; As[cv*4+3][row] = a.w;
        }
        #pragma unroll
        for (int it = 0; it < BITER; it++) {
            int v   = tid + it*THREADS;
            int row = v / (BN/4);
            int cv  = v % (BN/4);
            *(float4*)(&Bs[row][cv*4]) =
                *(const float4*)(Bm + (size_t)(k0+row)*N + n0 + cv*4);
        }
        __syncthreads();
        #pragma unroll
        for (int k = 0; k < BK; k++) {
            float rm[TM], rn[TN];
            #pragma unroll
            for (int i = 0; i < TM; i += 4) {
                float4 r = *(const float4*)(&As[k][tRow*TM + i]);
                rm[i] = r.x; rm[i+1] = r.y; rm[i+2] = r.z; rm[i+3] = r.w;
            }
            #pragma unroll
            for (int j = 0; j < TN; j += 4) {
                float4 r = *(const float4*)(&Bs[k][tCol*TN + j]);
                rn[j] = r.x; rn[j+1] = r.y; rn[j+2] = r.z; rn[j+3] = r.w;
            }
            #pragma unroll
            for (int i = 0; i < TM; i++)
                #pragma unroll
                for (int j = 0; j < TN; j++) acc[i][j] += rm[i]*rn[j];
        }
        __syncthreads();
    }
    #pragma unroll
    for (int i = 0; i < TM; i++) {
        float* cp = C + (size_t)(m0 + tRow*TM + i)*N + n0 + tCol*TN;
        #pragma unroll
        for (int j = 0; j < TN; j += 4) {
            float4 r = make_float4(acc[i][j], acc[i][j+1], acc[i][j+2], acc[i][j+3]);
            if (RESID) {
                float4 c = *(const float4*)(cp + j);
                r.x += c.x; r.y += c.y; r.z += c.z; r.w += c.w;
            }
            *(float4*)(cp + j) = r;
        }
    }
}

// ---------------- depthwise causal conv(4) + SiLU ----------------
__global__ void conv_silu_kernel(const float* __restrict__ xr, const float* __restrict__ cw,
                                 const float* __restrict__ cb, float* __restrict__ u)
{
    int d  = blockIdx.x * 256 + threadIdx.x;   // 0..511 (gridDim.x=2)
    int l0 = blockIdx.y * 64;                  // gridDim.y=16
    int b  = blockIdx.z;                       // gridDim.z=16
    float4 w   = *(const float4*)(cw + d*4);
    float bias = cb[d];
    const float* xs = xr + ((size_t)b*SEQL)*(2*DI) + d;
    float h0 = (l0 >= 3) ? xs[(size_t)(l0-3)*(2*DI)] : 0.f;
    float h1 = (l0 >= 2) ? xs[(size_t)(l0-2)*(2*DI)] : 0.f;
    float h2 = (l0 >= 1) ? xs[(size_t)(l0-1)*(2*DI)] : 0.f;
    float* up = u + ((size_t)b*SEQL + l0)*DI + d;
    #pragma unroll 4
    for (int i = 0; i < 64; i++) {
        float cur = xs[(size_t)(l0+i)*(2*DI)];
        float z = bias + w.x*h0 + w.y*h1 + w.z*h2 + w.w*cur;
        up[(size_t)i*DI] = z / (1.f + __expf(-z));
        h0 = h1; h1 = h2; h2 = cur;
    }
}

// ---------------- dt_proj + softplus + delta*u (fused) ----------------
__global__ void dt_kernel(const float* __restrict__ dbc, const float* __restrict__ dtw,
                          const float* __restrict__ dtb, const float* __restrict__ u,
                          float* __restrict__ delta, float* __restrict__ du)
{
    __shared__ float sd[DR];
    int t   = blockIdx.x;       // token
    int tid = threadIdx.x;      // 128
    if (tid < DR) sd[tid] = dbc[(size_t)t*64 + tid];
    __syncthreads();
    #pragma unroll
    for (int jj = 0; jj < 4; jj++) {
        int d = tid + jj*128;
        float acc = dtb[d];
        #pragma unroll
        for (int r = 0; r < DR; r++) acc += sd[r] * dtw[r*DI + d];
        float dl = (acc > 15.f) ? acc : log1pf(__expf(acc));
        size_t idx = (size_t)t*DI + d;
        delta[idx] = dl;
        du[idx]    = dl * u[idx];
    }
}

// ---------------- selective scan (seq-sequential; fused (y+u*D)*silu(res)) ----------------
__global__ void scan_kernel(const float* __restrict__ delta, const float* __restrict__ du,
                            const float* __restrict__ uu,    const float* __restrict__ xr,
                            const float* __restrict__ dbc,   const float* __restrict__ Alog,
                            const float* __restrict__ Dp,    float* __restrict__ y)
{
    int b = blockIdx.x >> 3;
    int g = blockIdx.x & 7;
    int d = g*64 + threadIdx.x;        // 64 threads/block

    float a[DS];
    #pragma unroll
    for (int n = 0; n < DS; n++) a[n] = -__expf(Alog[d*DS + n]);
    float Dv = Dp[d];
    float h[DS];
    #pragma unroll
    for (int n = 0; n < DS; n++) h[n] = 0.f;

    const float* dptr  = delta + (size_t)b*SEQL*DI + d;
    const float* duptr = du    + (size_t)b*SEQL*DI + d;
    const float* uptr  = uu    + (size_t)b*SEQL*DI + d;
    const float* rptr  = xr    + (size_t)b*SEQL*2*DI + DI + d;
    const float* bcptr = dbc   + (size_t)b*SEQL*64;
    float*       yptr  = y     + (size_t)b*SEQL*DI + d;

    for (int l = 0; l < SEQL; l++) {
        float dl  = dptr [(size_t)l*DI];
        float duv = duptr[(size_t)l*DI];
        float uv  = uptr [(size_t)l*DI];
        float res = rptr [(size_t)l*2*DI];
        const float4* Bv = (const float4*)(bcptr + (size_t)l*64 + 16);
        const float4* Cv = (const float4*)(bcptr + (size_t)l*64 + 32);
        float yv = 0.f;
        #pragma unroll
        for (int q = 0; q < 4; q++) {
            float4 Bq = Bv[q], Cq = Cv[q];
            float dA;
            dA = __expf(dl*a[4*q+0]); h[4*q+0] = dA*h[4*q+0] + duv*Bq.x; yv += h[4*q+0]*Cq.x;
            dA = __expf(dl*a[4*q+1]); h[4*q+1] = dA*h[4*q+1] + duv*Bq.y; yv += h[4*q+1]*Cq.y;
            dA = __expf(dl*a[4*q+2]); h[4*q+2] = dA*h[4*q+2] + duv*Bq.z; yv += h[4*q+2]*Cq.z;
            dA = __expf(dl*a[4*q+3]); h[4*q+3] = dA*h[4*q+3] + duv*Bq.w; yv += h[4*q+3]*Cq.w;
        }
        float o = yv + uv*Dv;
        o *= res / (1.f + __expf(-res));
        yptr[(size_t)l*DI] = o;
    }
}

// ---------------- pad x_proj_w (L,512,48) -> (L,512,64) zero-padded ----------------
__global__ void pad_xpw_kernel(const float* __restrict__ xpw, float* __restrict__ out)
{
    int idx = blockIdx.x * 256 + threadIdx.x;  // 4*512*64 = 131072
    int j  = idx & 63;
    int rk = idx >> 6;
    out[idx] = (j < 48) ? xpw[rk*48 + j] : 0.f;
}

// ---------------- deterministic two-stage mean over L ----------------
__global__ void mean_part_kernel(const float* __restrict__ seq, float* __restrict__ part)
{
    int b = blockIdx.x, c = blockIdx.y, e = threadIdx.x;
    const float* p = seq + ((size_t)b*SEQL + c*64)*DM + e;
    float s = 0.f;
    #pragma unroll 8
    for (int i = 0; i < 64; i++) s += p[(size_t)i*DM];
    part[(b*16 + c)*DM + e] = s;
}
__global__ void mean_final_kernel(const float* __restrict__ part, float* __restrict__ out)
{
    int b = blockIdx.x, e = threadIdx.x;
    float s = 0.f;
    #pragma unroll
    for (int c = 0; c < 16; c++) s += part[(b*16 + c)*DM + e];
    out[b*DM + e] = s * (1.f/1024.f);
}

// ---------------- launch ----------------
extern "C" void kernel_launch(void* const* d_in, const int* in_sizes, int n_in,
                              void* d_out, int out_size)
{
    const float* x    = (const float*)d_in[0];
    const float* plg  = (const float*)d_in[1];
    const float* plb  = (const float*)d_in[2];
    const float* ew   = (const float*)d_in[3];
    const float* eb   = (const float*)d_in[4];
    const float* elg  = (const float*)d_in[5];
    const float* elb  = (const float*)d_in[6];
    const float* rmsw = (const float*)d_in[7];
    const float* inw  = (const float*)d_in[8];
    const float* cw   = (const float*)d_in[9];
    const float* cb   = (const float*)d_in[10];
    const float* xpw  = (const float*)d_in[11];
    const float* dtw  = (const float*)d_in[12];
    const float* dtb  = (const float*)d_in[13];
    const float* Alog = (const float*)d_in[14];
    const float* Dpar = (const float*)d_in[15];
    const float* ow   = (const float*)d_in[16];

    float *seq, *xn, *xr, *u, *dbc, *delta, *du, *y, *xpwp, *part;
    cudaGetSymbolAddress((void**)&seq,   g_seq);
    cudaGetSymbolAddress((void**)&xn,    g_xn);
    cudaGetSymbolAddress((void**)&xr,    g_xr);
    cudaGetSymbolAddress((void**)&u,     g_u);
    cudaGetSymbolAddress((void**)&dbc,   g_dbc);
    cudaGetSymbolAddress((void**)&delta, g_delta);
    cudaGetSymbolAddress((void**)&du,    g_du);
    cudaGetSymbolAddress((void**)&y,     g_y);
    cudaGetSymbolAddress((void**)&xpwp,  g_xpw);
    cudaGetSymbolAddress((void**)&part,  g_part);

    const int M = BATCH * SEQL;  // 16384

    pad_xpw_kernel<<<512, 256>>>(xpw, xpwp);
    patch_embed_kernel<<<2048, 256>>>(x, plg, plb, ew, eb, elg, elb, seq);

    for (int L = 0; L < NL; L++) {
        rmsnorm_kernel<<<2048, 256>>>(seq, rmsw + L*DM, xn);

        // in_proj: (16384,256) @ (256,1024) -> xr
        gemm_kernel<128,64,16,8,4,false><<<dim3(1024/64, M/128), 256>>>(
            xn, inw + (size_t)L*DM*2*DI, xr, M, 2*DI, DM);

        conv_silu_kernel<<<dim3(2,16,16), 256>>>(xr, cw + L*DI*4, cb + L*DI, u);

        // x_proj: (16384,512) @ (512,64pad) -> dbc
        gemm_kernel<128,64,16,8,4,false><<<dim3(1, M/128), 256>>>(
            u, xpwp + (size_t)L*DI*64, dbc, M, 64, DI);

        dt_kernel<<<M, 128>>>(dbc, dtw + L*DR*DI, dtb + L*DI, u, delta, du);

        scan_kernel<<<128, 64>>>(delta, du, u, xr, dbc,
                                 Alog + L*DI*DS, Dpar + L*DI, y);

        // out_proj (+residual into seq): (16384,512) @ (512,256)
        gemm_kernel<128,64,16,8,4,true><<<dim3(DM/64, M/128), 256>>>(
            y, ow + (size_t)L*DI*DM, seq, M, DM, DI);
    }

    mean_part_kernel<<<dim3(16,16), 256>>>(seq, part);
    mean_final_kernel<<<16, 256>>>(part, (float*)d_out);
}

// round 2
// speedup vs baseline: 3.1592x; 3.1592x over previous
#include <cuda_runtime.h>
#include <math.h>

#define BATCH 16
#define SEQL  1024
#define DM    256
#define DI    512
#define DS    16
#define DR    16
#define NL    4
#define NC    16        // scan chunks
#define CL    (SEQL/NC) // 64 steps per chunk

// ---------------- scratch (static device globals; no allocation) ----------------
__device__ float g_seq  [BATCH*SEQL*DM];
__device__ float g_xn   [BATCH*SEQL*DM];
__device__ float g_xr   [BATCH*SEQL*2*DI];
__device__ float g_u    [BATCH*SEQL*DI];
__device__ float g_dbc  [BATCH*SEQL*64];
__device__ float g_delta[BATCH*SEQL*DI];
__device__ float g_du   [BATCH*SEQL*DI];
__device__ float g_y    [BATCH*SEQL*DI];
__device__ float g_xpw  [NL*DI*64];
__device__ float g_part [BATCH*16*DM];
__device__ float g_ca   [BATCH*NC*DI*DS];   // per-chunk cumulative A product
__device__ float g_cs   [BATCH*NC*DI*DS];   // per-chunk local state
__device__ float g_h0   [BATCH*NC*DI*DS];   // per-chunk initial state

__device__ __forceinline__ float ex2f(float x) {
    float r; asm("ex2.approx.f32 %0, %1;" : "=f"(r) : "f"(x)); return r;
}

// ---------------- patch extract + LN(48) + embed(48->256) + LN(256) ----------------
__global__ void patch_embed_kernel(const float* __restrict__ x,
                                   const float* __restrict__ plg, const float* __restrict__ plb,
                                   const float* __restrict__ ew,  const float* __restrict__ eb,
                                   const float* __restrict__ elg, const float* __restrict__ elb,
                                   float* __restrict__ seq)
{
    __shared__ float sp[8][48];
    int warp = threadIdx.x >> 5, lane = threadIdx.x & 31;
    int t = blockIdx.x * 8 + warp;
    int b = t >> 10, pos = t & 1023;
    int hy = pos >> 5, wx = pos & 31;

    float p1, p2 = 0.f;
    {
        int j = lane;
        int c = j >> 4, py = (j >> 2) & 3, px = j & 3;
        p1 = x[((b*3 + c)*128 + hy*4 + py)*128 + wx*4 + px];
        if (lane < 16) {
            j = 32 + lane;
            c = j >> 4; py = (j >> 2) & 3; px = j & 3;
            p2 = x[((b*3 + c)*128 + hy*4 + py)*128 + wx*4 + px];
        }
    }
    float s = p1 + p2, ss = p1*p1 + p2*p2;
    #pragma unroll
    for (int o = 16; o > 0; o >>= 1) {
        s  += __shfl_xor_sync(0xffffffffu, s,  o);
        ss += __shfl_xor_sync(0xffffffffu, ss, o);
    }
    float mu  = s * (1.f/48.f);
    float var = ss * (1.f/48.f) - mu*mu;
    float rs  = rsqrtf(var + 1e-5f);
    sp[warp][lane] = (p1 - mu)*rs*plg[lane] + plb[lane];
    if (lane < 16) sp[warp][32+lane] = (p2 - mu)*rs*plg[32+lane] + plb[32+lane];
    __syncwarp();

    float acc[8];
    #pragma unroll
    for (int i = 0; i < 8; i++) acc[i] = eb[lane + 32*i];
    #pragma unroll 4
    for (int j = 0; j < 48; j++) {
        float v = sp[warp][j];
        const float* w = ew + j*DM + lane;
        #pragma unroll
        for (int i = 0; i < 8; i++) acc[i] += v * w[32*i];
    }
    float s2 = 0.f, ss2 = 0.f;
    #pragma unroll
    for (int i = 0; i < 8; i++) { s2 += acc[i]; ss2 += acc[i]*acc[i]; }
    #pragma unroll
    for (int o = 16; o > 0; o >>= 1) {
        s2  += __shfl_xor_sync(0xffffffffu, s2,  o);
        ss2 += __shfl_xor_sync(0xffffffffu, ss2, o);
    }
    float mu2  = s2 * (1.f/256.f);
    float var2 = ss2 * (1.f/256.f) - mu2*mu2;
    float rs2  = rsqrtf(var2 + 1e-5f);
    #pragma unroll
    for (int i = 0; i < 8; i++) {
        int e = lane + 32*i;
        seq[(size_t)t*DM + e] = (acc[i] - mu2)*rs2*elg[e] + elb[e];
    }
}

// ---------------- rmsnorm over DM=256 (warp per token) ----------------
__global__ void rmsnorm_kernel(const float* __restrict__ in, const float* __restrict__ w,
                               float* __restrict__ out)
{
    int warp = threadIdx.x >> 5, lane = threadIdx.x & 31;
    int t = blockIdx.x * 8 + warp;
    const float4* ip = (const float4*)(in + (size_t)t*DM);
    float4 v0 = ip[lane], v1 = ip[lane+32];
    float ss = v0.x*v0.x+v0.y*v0.y+v0.z*v0.z+v0.w*v0.w
             + v1.x*v1.x+v1.y*v1.y+v1.z*v1.z+v1.w*v1.w;
    #pragma unroll
    for (int o = 16; o > 0; o >>= 1) ss += __shfl_xor_sync(0xffffffffu, ss, o);
    float sc = rsqrtf(ss*(1.f/256.f) + 1e-5f);
    const float4* wp = (const float4*)w;
    float4 w0 = wp[lane], w1 = wp[lane+32];
    float4 o0 = make_float4(v0.x*sc*w0.x, v0.y*sc*w0.y, v0.z*sc*w0.z, v0.w*sc*w0.w);
    float4 o1 = make_float4(v1.x*sc*w1.x, v1.y*sc*w1.y, v1.z*sc*w1.z, v1.w*sc*w1.w);
    float4* op = (float4*)(out + (size_t)t*DM);
    op[lane] = o0; op[lane+32] = o1;
}

// ---------------- generic fp32 GEMM: C[M,N] = A[M,K] @ B[K,N] (+C if RESID) ----------------
template<int BM, int BN, int BK, int TM, int TN, bool RESID>
__global__ void __launch_bounds__((BM/TM)*(BN/TN))
gemm_kernel(const float* __restrict__ A, const float* __restrict__ Bm,
            float* __restrict__ C, int M, int N, int K)
{
    constexpr int THREADS = (BM/TM)*(BN/TN);
    __shared__ float As[BK][BM+4];
    __shared__ float Bs[BK][BN];
    const int tid = threadIdx.x;
    const int m0 = blockIdx.y * BM;
    const int n0 = blockIdx.x * BN;
    const int tRow = tid / (BN/TN);
    const int tCol = tid % (BN/TN);

    float acc[TM][TN];
    #pragma unroll
    for (int i = 0; i < TM; i++)
        #pragma unroll
        for (int j = 0; j < TN; j++) acc[i][j] = 0.f;

    constexpr int AITER = (BM*BK/4) / THREADS;
    constexpr int BITER = (BK*BN/4) / THREADS;

    for (int k0 = 0; k0 < K; k0 += BK) {
        #pragma unroll
        for (int it = 0; it < AITER; it++) {
            int v   = tid + it*THREADS;
            int row = v / (BK/4);
            int cv  = v % (BK/4);
            float4 a = *(const float4*)(A + (size_t)(m0+row)*K + k0 + cv*4);
            As[cv*4+0][row] = a.x; As[cv*4+1][row] = a.y;
            As[cv*4+2][row] = a.z; As[cv*4+3][row] = a.w;
        }
        #pragma unroll
        for (int it = 0; it < BITER; it++) {
            int v   = tid + it*THREADS;
            int row = v / (BN/4);
            int cv  = v % (BN/4);
            *(float4*)(&Bs[row][cv*4]) =
                *(const float4*)(Bm + (size_t)(k0+row)*N + n0 + cv*4);
        }
        __syncthreads();
        #pragma unroll
        for (int k = 0; k < BK; k++) {
            float rm[TM], rn[TN];
            #pragma unroll
            for (int i = 0; i < TM; i += 4) {
                float4 r = *(const float4*)(&As[k][tRow*TM + i]);
                rm[i] = r.x; rm[i+1] = r.y; rm[i+2] = r.z; rm[i+3] = r.w;
            }
            #pragma unroll
            for (int j = 0; j < TN; j += 4) {
                float4 r = *(const float4*)(&Bs[k][tCol*TN + j]);
                rn[j] = r.x; rn[j+1] = r.y; rn[j+2] = r.z; rn[j+3] = r.w;
            }
            #pragma unroll
            for (int i = 0; i < TM; i++)
                #pragma unroll
                for (int j = 0; j < TN; j++) acc[i][j] += rm[i]*rn[j];
        }
        __syncthreads();
    }
    #pragma unroll
    for (int i = 0; i < TM; i++) {
        float* cp = C + (size_t)(m0 + tRow*TM + i)*N + n0 + tCol*TN;
        #pragma unroll
        for (int j = 0; j < TN; j += 4) {
            float4 r = make_float4(acc[i][j], acc[i][j+1], acc[i][j+2], acc[i][j+3]);
            if (RESID) {
                float4 c = *(const float4*)(cp + j);
                r.x += c.x; r.y += c.y; r.z += c.z; r.w += c.w;
            }
            *(float4*)(cp + j) = r;
        }
    }
}

// ---------------- depthwise causal conv(4) + SiLU ----------------
__global__ void conv_silu_kernel(const float* __restrict__ xr, const float* __restrict__ cw,
                                 const float* __restrict__ cb, float* __restrict__ u)
{
    int d  = blockIdx.x * 256 + threadIdx.x;
    int l0 = blockIdx.y * 64;
    int b  = blockIdx.z;
    float4 w   = *(const float4*)(cw + d*4);
    float bias = cb[d];
    const float* xs = xr + ((size_t)b*SEQL)*(2*DI) + d;
    float h0 = (l0 >= 3) ? xs[(size_t)(l0-3)*(2*DI)] : 0.f;
    float h1 = (l0 >= 2) ? xs[(size_t)(l0-2)*(2*DI)] : 0.f;
    float h2 = (l0 >= 1) ? xs[(size_t)(l0-1)*(2*DI)] : 0.f;
    float* up = u + ((size_t)b*SEQL + l0)*DI + d;
    #pragma unroll 4
    for (int i = 0; i < 64; i++) {
        float cur = xs[(size_t)(l0+i)*(2*DI)];
        float z = bias + w.x*h0 + w.y*h1 + w.z*h2 + w.w*cur;
        up[(size_t)i*DI] = z / (1.f + __expf(-z));
        h0 = h1; h1 = h2; h2 = cur;
    }
}

// ---------------- dt_proj + softplus + delta*u (fused) ----------------
__global__ void dt_kernel(const float* __restrict__ dbc, const float* __restrict__ dtw,
                          const float* __restrict__ dtb, const float* __restrict__ u,
                          float* __restrict__ delta, float* __restrict__ du)
{
    __shared__ float sd[DR];
    int t   = blockIdx.x;
    int tid = threadIdx.x;
    if (tid < DR) sd[tid] = dbc[(size_t)t*64 + tid];
    __syncthreads();
    #pragma unroll
    for (int jj = 0; jj < 4; jj++) {
        int d = tid + jj*128;
        float acc = dtb[d];
        #pragma unroll
        for (int r = 0; r < DR; r++) acc += sd[r] * dtw[r*DI + d];
        float dl = (acc > 15.f) ? acc : log1pf(__expf(acc));
        size_t idx = (size_t)t*DI + d;
        delta[idx] = dl;
        du[idx]    = dl * u[idx];
    }
}

// ---------------- chunked selective scan: pass 1 (local scan per chunk) ----------------
__global__ void __launch_bounds__(128)
scan_pass1(const float* __restrict__ delta, const float* __restrict__ du,
           const float* __restrict__ dbc,   const float* __restrict__ Alog,
           float* __restrict__ ca, float* __restrict__ cs)
{
    int d = blockIdx.x * 128 + threadIdx.x;   // 0..511
    int c = blockIdx.y;                       // chunk
    int b = blockIdx.z;

    float a2[DS];
    #pragma unroll
    for (int n = 0; n < DS; n++) a2[n] = -__expf(Alog[d*DS + n]) * 1.44269504f;

    float p[DS], s[DS];
    #pragma unroll
    for (int n = 0; n < DS; n++) { p[n] = 1.f; s[n] = 0.f; }

    const float* dptr  = delta + ((size_t)b*SEQL + c*CL)*DI + d;
    const float* duptr = du    + ((size_t)b*SEQL + c*CL)*DI + d;
    const float* bc    = dbc   + ((size_t)b*SEQL + c*CL)*64;

    for (int l = 0; l < CL; l++) {
        float dl  = dptr [(size_t)l*DI];
        float duv = duptr[(size_t)l*DI];
        const float4* Bv = (const float4*)(bc + (size_t)l*64 + 16);
        #pragma unroll
        for (int q = 0; q < 4; q++) {
            float4 Bq = Bv[q];
            float e;
            e = ex2f(dl*a2[4*q+0]); p[4*q+0]*=e; s[4*q+0]=e*s[4*q+0]+duv*Bq.x;
            e = ex2f(dl*a2[4*q+1]); p[4*q+1]*=e; s[4*q+1]=e*s[4*q+1]+duv*Bq.y;
            e = ex2f(dl*a2[4*q+2]); p[4*q+2]*=e; s[4*q+2]=e*s[4*q+2]+duv*Bq.z;
            e = ex2f(dl*a2[4*q+3]); p[4*q+3]*=e; s[4*q+3]=e*s[4*q+3]+duv*Bq.w;
        }
    }
    size_t o = (((size_t)b*NC + c)*DI + d)*DS;
    #pragma unroll
    for (int q = 0; q < 4; q++) {
        ((float4*)(ca + o))[q] = make_float4(p[4*q], p[4*q+1], p[4*q+2], p[4*q+3]);
        ((float4*)(cs + o))[q] = make_float4(s[4*q], s[4*q+1], s[4*q+2], s[4*q+3]);
    }
}

// ---------------- pass 2: combine chunk transitions -> h0 per chunk ----------------
__global__ void __launch_bounds__(DI)
scan_pass2(const float* __restrict__ ca, const float* __restrict__ cs,
           float* __restrict__ h0)
{
    int b = blockIdx.x, d = threadIdx.x;
    float h[DS];
    #pragma unroll
    for (int n = 0; n < DS; n++) h[n] = 0.f;
    for (int c = 0; c < NC; c++) {
        size_t o = (((size_t)b*NC + c)*DI + d)*DS;
        #pragma unroll
        for (int q = 0; q < 4; q++)
            ((float4*)(h0 + o))[q] = make_float4(h[4*q], h[4*q+1], h[4*q+2], h[4*q+3]);
        #pragma unroll
        for (int q = 0; q < 4; q++) {
            float4 pq = ((const float4*)(ca + o))[q];
            float4 sq = ((const float4*)(cs + o))[q];
            h[4*q+0] = pq.x*h[4*q+0] + sq.x;
            h[4*q+1] = pq.y*h[4*q+1] + sq.y;
            h[4*q+2] = pq.z*h[4*q+2] + sq.z;
            h[4*q+3] = pq.w*h[4*q+3] + sq.w;
        }
    }
}

// ---------------- pass 3: re-scan chunk from h0, emit y with fused epilogue ----------------
__global__ void __launch_bounds__(128)
scan_pass3(const float* __restrict__ delta, const float* __restrict__ du,
           const float* __restrict__ uu,    const float* __restrict__ xr,
           const float* __restrict__ dbc,   const float* __restrict__ Alog,
           const float* __restrict__ Dp,    const float* __restrict__ h0,
           float* __restrict__ y)
{
    int d = blockIdx.x * 128 + threadIdx.x;
    int c = blockIdx.y;
    int b = blockIdx.z;

    float a2[DS];
    #pragma unroll
    for (int n = 0; n < DS; n++) a2[n] = -__expf(Alog[d*DS + n]) * 1.44269504f;
    float Dv = Dp[d];

    float h[DS];
    {
        size_t o = (((size_t)b*NC + c)*DI + d)*DS;
        #pragma unroll
        for (int q = 0; q < 4; q++) {
            float4 hq = ((const float4*)(h0 + o))[q];
            h[4*q] = hq.x; h[4*q+1] = hq.y; h[4*q+2] = hq.z; h[4*q+3] = hq.w;
        }
    }

    const float* dptr  = delta + ((size_t)b*SEQL + c*CL)*DI + d;
    const float* duptr = du    + ((size_t)b*SEQL + c*CL)*DI + d;
    const float* uptr  = uu    + ((size_t)b*SEQL + c*CL)*DI + d;
    const float* rptr  = xr    + ((size_t)b*SEQL + c*CL)*2*DI + DI + d;
    const float* bc    = dbc   + ((size_t)b*SEQL + c*CL)*64;
    float*       yptr  = y     + ((size_t)b*SEQL + c*CL)*DI + d;

    for (int l = 0; l < CL; l++) {
        float dl  = dptr [(size_t)l*DI];
        float duv = duptr[(size_t)l*DI];
        float uv  = uptr [(size_t)l*DI];
        float res = rptr [(size_t)l*2*DI];
        const float4* Bv = (const float4*)(bc + (size_t)l*64 + 16);
        const float4* Cv = (const float4*)(bc + (size_t)l*64 + 32);
        float yv = 0.f;
        #pragma unroll
        for (int q = 0; q < 4; q++) {
            float4 Bq = Bv[q], Cq = Cv[q];
            float e;
            e = ex2f(dl*a2[4*q+0]); h[4*q+0]=e*h[4*q+0]+duv*Bq.x; yv += h[4*q+0]*Cq.x;
            e = ex2f(dl*a2[4*q+1]); h[4*q+1]=e*h[4*q+1]+duv*Bq.y; yv += h[4*q+1]*Cq.y;
            e = ex2f(dl*a2[4*q+2]); h[4*q+2]=e*h[4*q+2]+duv*Bq.z; yv += h[4*q+2]*Cq.z;
            e = ex2f(dl*a2[4*q+3]); h[4*q+3]=e*h[4*q+3]+duv*Bq.w; yv += h[4*q+3]*Cq.w;
        }
        float o = yv + uv*Dv;
        o *= res / (1.f + __expf(-res));
        yptr[(size_t)l*DI] = o;
    }
}

// ---------------- pad x_proj_w (L,512,48) -> (L,512,64) zero-padded ----------------
__global__ void pad_xpw_kernel(const float* __restrict__ xpw, float* __restrict__ out)
{
    int idx = blockIdx.x * 256 + threadIdx.x;
    int j  = idx & 63;
    int rk = idx >> 6;
    out[idx] = (j < 48) ? xpw[rk*48 + j] : 0.f;
}

// ---------------- deterministic two-stage mean over L ----------------
__global__ void mean_part_kernel(const float* __restrict__ seq, float* __restrict__ part)
{
    int b = blockIdx.x, c = blockIdx.y, e = threadIdx.x;
    const float* p = seq + ((size_t)b*SEQL + c*64)*DM + e;
    float s = 0.f;
    #pragma unroll 8
    for (int i = 0; i < 64; i++) s += p[(size_t)i*DM];
    part[(b*16 + c)*DM + e] = s;
}
__global__ void mean_final_kernel(const float* __restrict__ part, float* __restrict__ out)
{
    int b = blockIdx.x, e = threadIdx.x;
    float s = 0.f;
    #pragma unroll
    for (int c = 0; c < 16; c++) s += part[(b*16 + c)*DM + e];
    out[b*DM + e] = s * (1.f/1024.f);
}

// ---------------- launch ----------------
extern "C" void kernel_launch(void* const* d_in, const int* in_sizes, int n_in,
                              void* d_out, int out_size)
{
    const float* x    = (const float*)d_in[0];
    const float* plg  = (const float*)d_in[1];
    const float* plb  = (const float*)d_in[2];
    const float* ew   = (const float*)d_in[3];
    const float* eb   = (const float*)d_in[4];
    const float* elg  = (const float*)d_in[5];
    const float* elb  = (const float*)d_in[6];
    const float* rmsw = (const float*)d_in[7];
    const float* inw  = (const float*)d_in[8];
    const float* cw   = (const float*)d_in[9];
    const float* cb   = (const float*)d_in[10];
    const float* xpw  = (const float*)d_in[11];
    const float* dtw  = (const float*)d_in[12];
    const float* dtb  = (const float*)d_in[13];
    const float* Alog = (const float*)d_in[14];
    const float* Dpar = (const float*)d_in[15];
    const float* ow   = (const float*)d_in[16];

    float *seq, *xn, *xr, *u, *dbc, *delta, *du, *y, *xpwp, *part, *ca, *cs, *h0;
    cudaGetSymbolAddress((void**)&seq,   g_seq);
    cudaGetSymbolAddress((void**)&xn,    g_xn);
    cudaGetSymbolAddress((void**)&xr,    g_xr);
    cudaGetSymbolAddress((void**)&u,     g_u);
    cudaGetSymbolAddress((void**)&dbc,   g_dbc);
    cudaGetSymbolAddress((void**)&delta, g_delta);
    cudaGetSymbolAddress((void**)&du,    g_du);
    cudaGetSymbolAddress((void**)&y,     g_y);
    cudaGetSymbolAddress((void**)&xpwp,  g_xpw);
    cudaGetSymbolAddress((void**)&part,  g_part);
    cudaGetSymbolAddress((void**)&ca,    g_ca);
    cudaGetSymbolAddress((void**)&cs,    g_cs);
    cudaGetSymbolAddress((void**)&h0,    g_h0);

    const int M = BATCH * SEQL;  // 16384

    pad_xpw_kernel<<<512, 256>>>(xpw, xpwp);
    patch_embed_kernel<<<2048, 256>>>(x, plg, plb, ew, eb, elg, elb, seq);

    for (int L = 0; L < NL; L++) {
        rmsnorm_kernel<<<2048, 256>>>(seq, rmsw + L*DM, xn);

        // in_proj: (16384,256) @ (256,1024)
        gemm_kernel<128,64,16,8,4,false><<<dim3(1024/64, M/128), 256>>>(
            xn, inw + (size_t)L*DM*2*DI, xr, M, 2*DI, DM);

        conv_silu_kernel<<<dim3(2,16,16), 256>>>(xr, cw + L*DI*4, cb + L*DI, u);

        // x_proj: (16384,512) @ (512,64pad)  — 64x64 tiles for 256 blocks
        gemm_kernel<64,64,16,4,4,false><<<dim3(1, M/64), 256>>>(
            u, xpwp + (size_t)L*DI*64, dbc, M, 64, DI);

        dt_kernel<<<M, 128>>>(dbc, dtw + L*DR*DI, dtb + L*DI, u, delta, du);

        scan_pass1<<<dim3(4, NC, BATCH), 128>>>(delta, du, dbc, Alog + L*DI*DS, ca, cs);
        scan_pass2<<<BATCH, DI>>>(ca, cs, h0);
        scan_pass3<<<dim3(4, NC, BATCH), 128>>>(delta, du, u, xr, dbc,
                                                Alog + L*DI*DS, Dpar + L*DI, h0, y);

        // out_proj (+residual into seq): (16384,512) @ (512,256)
        gemm_kernel<128,64,16,8,4,true><<<dim3(DM/64, M/128), 256>>>(
            y, ow + (size_t)L*DI*DM, seq, M, DM, DI);
    }

    mean_part_kernel<<<dim3(16,16), 256>>>(seq, part);
    mean_final_kernel<<<16, 256>>>(part, (float*)d_out);
}

// round 3
// speedup vs baseline: 4.0253x; 1.2742x over previous
#include <cuda_runtime.h>
#include <math.h>

#define BATCH 16
#define SEQL  1024
#define DM    256
#define DI    512
#define DS    16
#define DR    16
#define NL    4
#define NC    16        // scan chunks
#define CL    (SEQL/NC) // 64 steps per chunk

// ---------------- scratch (static device globals; no allocation) ----------------
__device__ float g_seq  [BATCH*SEQL*DM];
__device__ float g_xn   [BATCH*SEQL*DM];
__device__ float g_xr   [BATCH*SEQL*2*DI];
__device__ float g_u    [BATCH*SEQL*DI];
__device__ float g_dbc  [BATCH*SEQL*64];
__device__ float g_y    [BATCH*SEQL*DI];
__device__ float g_xpw  [NL*DI*64];
__device__ float g_part [BATCH*16*DM];
__device__ float g_ca   [BATCH*NC*DI*DS];
__device__ float g_cs   [BATCH*NC*DI*DS];
__device__ float g_h0   [BATCH*NC*DI*DS];

__device__ __forceinline__ float ex2f(float x) {
    float r; asm("ex2.approx.f32 %0, %1;" : "=f"(r) : "f"(x)); return r;
}
__device__ __forceinline__ unsigned f2tf32(float f) {
    unsigned r; asm("cvt.rna.tf32.f32 %0, %1;" : "=r"(r) : "f"(f)); return r;
}

// ---------------- patch extract + LN(48) + embed(48->256) + LN(256) ----------------
__global__ void patch_embed_kernel(const float* __restrict__ x,
                                   const float* __restrict__ plg, const float* __restrict__ plb,
                                   const float* __restrict__ ew,  const float* __restrict__ eb,
                                   const float* __restrict__ elg, const float* __restrict__ elb,
                                   float* __restrict__ seq)
{
    __shared__ float sp[8][48];
    int warp = threadIdx.x >> 5, lane = threadIdx.x & 31;
    int t = blockIdx.x * 8 + warp;
    int b = t >> 10, pos = t & 1023;
    int hy = pos >> 5, wx = pos & 31;

    float p1, p2 = 0.f;
    {
        int j = lane;
        int c = j >> 4, py = (j >> 2) & 3, px = j & 3;
        p1 = x[((b*3 + c)*128 + hy*4 + py)*128 + wx*4 + px];
        if (lane < 16) {
            j = 32 + lane;
            c = j >> 4; py = (j >> 2) & 3; px = j & 3;
            p2 = x[((b*3 + c)*128 + hy*4 + py)*128 + wx*4 + px];
        }
    }
    float s = p1 + p2, ss = p1*p1 + p2*p2;
    #pragma unroll
    for (int o = 16; o > 0; o >>= 1) {
        s  += __shfl_xor_sync(0xffffffffu, s,  o);
        ss += __shfl_xor_sync(0xffffffffu, ss, o);
    }
    float mu  = s * (1.f/48.f);
    float var = ss * (1.f/48.f) - mu*mu;
    float rs  = rsqrtf(var + 1e-5f);
    sp[warp][lane] = (p1 - mu)*rs*plg[lane] + plb[lane];
    if (lane < 16) sp[warp][32+lane] = (p2 - mu)*rs*plg[32+lane] + plb[32+lane];
    __syncwarp();

    float acc[8];
    #pragma unroll
    for (int i = 0; i < 8; i++) acc[i] = eb[lane + 32*i];
    #pragma unroll 4
    for (int j = 0; j < 48; j++) {
        float v = sp[warp][j];
        const float* w = ew + j*DM + lane;
        #pragma unroll
        for (int i = 0; i < 8; i++) acc[i] += v * w[32*i];
    }
    float s2 = 0.f, ss2 = 0.f;
    #pragma unroll
    for (int i = 0; i < 8; i++) { s2 += acc[i]; ss2 += acc[i]*acc[i]; }
    #pragma unroll
    for (int o = 16; o > 0; o >>= 1) {
        s2  += __shfl_xor_sync(0xffffffffu, s2,  o);
        ss2 += __shfl_xor_sync(0xffffffffu, ss2, o);
    }
    float mu2  = s2 * (1.f/256.f);
    float var2 = ss2 * (1.f/256.f) - mu2*mu2;
    float rs2  = rsqrtf(var2 + 1e-5f);
    #pragma unroll
    for (int i = 0; i < 8; i++) {
        int e = lane + 32*i;
        seq[(size_t)t*DM + e] = (acc[i] - mu2)*rs2*elg[e] + elb[e];
    }
}

// ---------------- rmsnorm over DM=256 (warp per token) ----------------
__global__ void rmsnorm_kernel(const float* __restrict__ in, const float* __restrict__ w,
                               float* __restrict__ out)
{
    int warp = threadIdx.x >> 5, lane = threadIdx.x & 31;
    int t = blockIdx.x * 8 + warp;
    const float4* ip = (const float4*)(in + (size_t)t*DM);
    float4 v0 = ip[lane], v1 = ip[lane+32];
    float ss = v0.x*v0.x+v0.y*v0.y+v0.z*v0.z+v0.w*v0.w
             + v1.x*v1.x+v1.y*v1.y+v1.z*v1.z+v1.w*v1.w;
    #pragma unroll
    for (int o = 16; o > 0; o >>= 1) ss += __shfl_xor_sync(0xffffffffu, ss, o);
    float sc = rsqrtf(ss*(1.f/256.f) + 1e-5f);
    const float4* wp = (const float4*)w;
    float4 w0 = wp[lane], w1 = wp[lane+32];
    float4 o0 = make_float4(v0.x*sc*w0.x, v0.y*sc*w0.y, v0.z*sc*w0.z, v0.w*sc*w0.w);
    float4 o1 = make_float4(v1.x*sc*w1.x, v1.y*sc*w1.y, v1.z*sc*w1.z, v1.w*sc*w1.w);
    float4* op = (float4*)(out + (size_t)t*DM);
    op[lane] = o0; op[lane+32] = o1;
}

// ---------------- TF32 tensor-core GEMM: C[M,N] = A[M,K] @ B[K,N] (+C if RESID) ----------------
// BM=128, BN=64, BK=32, 256 threads (8 warps: 4 in M x 2 in N), warp tile 32x32.
template<bool RESID>
__global__ void __launch_bounds__(256)
gemm_tf32(const float* __restrict__ A, const float* __restrict__ Bm,
          float* __restrict__ C, int M, int N, int K)
{
    __shared__ unsigned As[32][136];   // K-major, pad 8
    __shared__ unsigned Bs[32][72];    // row k, pad 8
    const int tid  = threadIdx.x;
    const int m0   = blockIdx.y * 128;
    const int n0   = blockIdx.x * 64;
    const int warp = tid >> 5, lane = tid & 31;
    const int g = lane >> 2, t = lane & 3;
    const int wm = (warp & 3) * 32;
    const int wn = (warp >> 2) * 32;

    float acc[2][4][4];
    #pragma unroll
    for (int a = 0; a < 2; a++)
        #pragma unroll
        for (int b = 0; b < 4; b++)
            #pragma unroll
            for (int c = 0; c < 4; c++) acc[a][b][c] = 0.f;

    for (int k0 = 0; k0 < K; k0 += 32) {
        #pragma unroll
        for (int it = 0; it < 4; it++) {
            int v = tid + it*256;
            int row = v >> 3, cv = v & 7;
            float4 a = *(const float4*)(A + (size_t)(m0+row)*K + k0 + cv*4);
            As[cv*4+0][row] = f2tf32(a.x);
            As[cv*4+1][row] = f2tf32(a.y);
            As[cv*4+2][row] = f2tf32(a.z);
            As[cv*4+3][row] = f2tf32(a.w);
        }
        #pragma unroll
        for (int it = 0; it < 2; it++) {
            int v = tid + it*256;
            int row = v >> 4, cv = v & 15;
            float4 bq = *(const float4*)(Bm + (size_t)(k0+row)*N + n0 + cv*4);
            Bs[row][cv*4+0] = f2tf32(bq.x);
            Bs[row][cv*4+1] = f2tf32(bq.y);
            Bs[row][cv*4+2] = f2tf32(bq.z);
            Bs[row][cv*4+3] = f2tf32(bq.w);
        }
        __syncthreads();
        #pragma unroll
        for (int kc = 0; kc < 4; kc++) {
            int kk = kc * 8;
            unsigned af[2][4], bf[4][2];
            #pragma unroll
            for (int mt = 0; mt < 2; mt++) {
                int r = wm + mt*16 + g;
                af[mt][0] = As[kk+t  ][r];
                af[mt][1] = As[kk+t  ][r+8];
                af[mt][2] = As[kk+t+4][r];
                af[mt][3] = As[kk+t+4][r+8];
            }
            #pragma unroll
            for (int nt = 0; nt < 4; nt++) {
                int cn = wn + nt*8 + g;
                bf[nt][0] = Bs[kk+t  ][cn];
                bf[nt][1] = Bs[kk+t+4][cn];
            }
            #pragma unroll
            for (int mt = 0; mt < 2; mt++)
                #pragma unroll
                for (int nt = 0; nt < 4; nt++) {
                    asm volatile(
                        "mma.sync.aligned.m16n8k8.row.col.f32.tf32.tf32.f32 "
                        "{%0,%1,%2,%3},{%4,%5,%6,%7},{%8,%9},{%0,%1,%2,%3};"
                        : "+f"(acc[mt][nt][0]), "+f"(acc[mt][nt][1]),
                          "+f"(acc[mt][nt][2]), "+f"(acc[mt][nt][3])
                        : "r"(af[mt][0]), "r"(af[mt][1]), "r"(af[mt][2]), "r"(af[mt][3]),
                          "r"(bf[nt][0]), "r"(bf[nt][1]));
                }
        }
        __syncthreads();
    }
    #pragma unroll
    for (int mt = 0; mt < 2; mt++)
        #pragma unroll
        for (int nt = 0; nt < 4; nt++) {
            int row = m0 + wm + mt*16 + g;
            int col = n0 + wn + nt*8 + 2*t;
            float* p0 = C + (size_t)row*N + col;
            float* p1 = C + (size_t)(row+8)*N + col;
            float2 v0 = make_float2(acc[mt][nt][0], acc[mt][nt][1]);
            float2 v1 = make_float2(acc[mt][nt][2], acc[mt][nt][3]);
            if (RESID) {
                float2 c0 = *(const float2*)p0, c1 = *(const float2*)p1;
                v0.x += c0.x; v0.y += c0.y; v1.x += c1.x; v1.y += c1.y;
            }
            *(float2*)p0 = v0;
            *(float2*)p1 = v1;
        }
}

// ---------------- exact fp32 SIMT GEMM (kept for x_proj) ----------------
template<int BM, int BN, int BK, int TM, int TN, bool RESID>
__global__ void __launch_bounds__((BM/TM)*(BN/TN))
gemm_kernel(const float* __restrict__ A, const float* __restrict__ Bm,
            float* __restrict__ C, int M, int N, int K)
{
    constexpr int THREADS = (BM/TM)*(BN/TN);
    __shared__ float As[BK][BM+4];
    __shared__ float Bs[BK][BN];
    const int tid = threadIdx.x;
    const int m0 = blockIdx.y * BM;
    const int n0 = blockIdx.x * BN;
    const int tRow = tid / (BN/TN);
    const int tCol = tid % (BN/TN);

    float acc[TM][TN];
    #pragma unroll
    for (int i = 0; i < TM; i++)
        #pragma unroll
        for (int j = 0; j < TN; j++) acc[i][j] = 0.f;

    constexpr int AITER = (BM*BK/4) / THREADS;
    constexpr int BITER = (BK*BN/4) / THREADS;

    for (int k0 = 0; k0 < K; k0 += BK) {
        #pragma unroll
        for (int it = 0; it < AITER; it++) {
            int v   = tid + it*THREADS;
            int row = v / (BK/4);
            int cv  = v % (BK/4);
            float4 a = *(const float4*)(A + (size_t)(m0+row)*K + k0 + cv*4);
            As[cv*4+0][row] = a.x; As[cv*4+1][row] = a.y;
            As[cv*4+2][row] = a.z; As[cv*4+3][row] = a.w;
        }
        #pragma unroll
        for (int it = 0; it < BITER; it++) {
            int v   = tid + it*THREADS;
            int row = v / (BN/4);
            int cv  = v % (BN/4);
            *(float4*)(&Bs[row][cv*4]) =
                *(const float4*)(Bm + (size_t)(k0+row)*N + n0 + cv*4);
        }
        __syncthreads();
        #pragma unroll
        for (int k = 0; k < BK; k++) {
            float rm[TM], rn[TN];
            #pragma unroll
            for (int i = 0; i < TM; i += 4) {
                float4 r = *(const float4*)(&As[k][tRow*TM + i]);
                rm[i] = r.x; rm[i+1] = r.y; rm[i+2] = r.z; rm[i+3] = r.w;
            }
            #pragma unroll
            for (int j = 0; j < TN; j += 4) {
                float4 r = *(const float4*)(&Bs[k][tCol*TN + j]);
                rn[j] = r.x; rn[j+1] = r.y; rn[j+2] = r.z; rn[j+3] = r.w;
            }
            #pragma unroll
            for (int i = 0; i < TM; i++)
                #pragma unroll
                for (int j = 0; j < TN; j++) acc[i][j] += rm[i]*rn[j];
        }
        __syncthreads();
    }
    #pragma unroll
    for (int i = 0; i < TM; i++) {
        float* cp = C + (size_t)(m0 + tRow*TM + i)*N + n0 + tCol*TN;
        #pragma unroll
        for (int j = 0; j < TN; j += 4) {
            float4 r = make_float4(acc[i][j], acc[i][j+1], acc[i][j+2], acc[i][j+3]);
            if (RESID) {
                float4 c = *(const float4*)(cp + j);
                r.x += c.x; r.y += c.y; r.z += c.z; r.w += c.w;
            }
            *(float4*)(cp + j) = r;
        }
    }
}

// ---------------- depthwise causal conv(4) + SiLU ----------------
__global__ void conv_silu_kernel(const float* __restrict__ xr, const float* __restrict__ cw,
                                 const float* __restrict__ cb, float* __restrict__ u)
{
    int d  = blockIdx.x * 256 + threadIdx.x;
    int l0 = blockIdx.y * 64;
    int b  = blockIdx.z;
    float4 w   = *(const float4*)(cw + d*4);
    float bias = cb[d];
    const float* xs = xr + ((size_t)b*SEQL)*(2*DI) + d;
    float h0 = (l0 >= 3) ? xs[(size_t)(l0-3)*(2*DI)] : 0.f;
    float h1 = (l0 >= 2) ? xs[(size_t)(l0-2)*(2*DI)] : 0.f;
    float h2 = (l0 >= 1) ? xs[(size_t)(l0-1)*(2*DI)] : 0.f;
    float* up = u + ((size_t)b*SEQL + l0)*DI + d;
    #pragma unroll 4
    for (int i = 0; i < 64; i++) {
        float cur = xs[(size_t)(l0+i)*(2*DI)];
        float z = bias + w.x*h0 + w.y*h1 + w.z*h2 + w.w*cur;
        up[(size_t)i*DI] = z / (1.f + __expf(-z));
        h0 = h1; h1 = h2; h2 = cur;
    }
}

// ---- helpers shared by scan passes (dt_proj + softplus fused inline) ----
__device__ __forceinline__ float dt_softplus(const float4* dtv, const float* w, float bias)
{
    float4 t0 = dtv[0], t1 = dtv[1], t2 = dtv[2], t3 = dtv[3];
    float acc = bias;
    acc += t0.x*w[0]  + t0.y*w[1]  + t0.z*w[2]  + t0.w*w[3];
    acc += t1.x*w[4]  + t1.y*w[5]  + t1.z*w[6]  + t1.w*w[7];
    acc += t2.x*w[8]  + t2.y*w[9]  + t2.z*w[10] + t2.w*w[11];
    acc += t3.x*w[12] + t3.y*w[13] + t3.z*w[14] + t3.w*w[15];
    return (acc > 15.f) ? acc : log1pf(__expf(acc));
}

// ---------------- chunked scan pass 1: local cumA + local state ----------------
__global__ void __launch_bounds__(128)
scan_pass1(const float* __restrict__ u,  const float* __restrict__ dbc,
           const float* __restrict__ Alog, const float* __restrict__ dtw,
           const float* __restrict__ dtb,
           float* __restrict__ ca, float* __restrict__ cs)
{
    int d = blockIdx.x * 128 + threadIdx.x;
    int c = blockIdx.y;
    int b = blockIdx.z;

    float a2[DS];
    #pragma unroll
    for (int n = 0; n < DS; n++) a2[n] = -__expf(Alog[d*DS + n]) * 1.44269504f;
    bool chain = true;
    #pragma unroll
    for (int n = 1; n < DS; n++)
        if (fabsf(a2[n] - (float)(n+1)*a2[0]) > 1e-4f*fabsf(a2[n])) chain = false;

    float w[DR];
    #pragma unroll
    for (int r = 0; r < DR; r++) w[r] = dtw[r*DI + d];
    float bias = dtb[d];

    float p[DS], s[DS];
    #pragma unroll
    for (int n = 0; n < DS; n++) { p[n] = 1.f; s[n] = 0.f; }

    const float* bc   = dbc + ((size_t)b*SEQL + c*CL)*64;
    const float* uptr = u   + ((size_t)b*SEQL + c*CL)*DI + d;

    if (chain) {
        for (int l = 0; l < CL; l++) {
            const float4* dtv = (const float4*)(bc + (size_t)l*64);
            float dl  = dt_softplus(dtv, w, bias);
            float duv = dl * uptr[(size_t)l*DI];
            const float4* Bv = dtv + 4;
            float e1 = ex2f(dl*a2[0]);
            float e  = e1;
            #pragma unroll
            for (int q = 0; q < 4; q++) {
                float4 Bq = Bv[q];
                p[4*q+0]*=e; s[4*q+0]=e*s[4*q+0]+duv*Bq.x; e*=e1;
                p[4*q+1]*=e; s[4*q+1]=e*s[4*q+1]+duv*Bq.y; e*=e1;
                p[4*q+2]*=e; s[4*q+2]=e*s[4*q+2]+duv*Bq.z; e*=e1;
                p[4*q+3]*=e; s[4*q+3]=e*s[4*q+3]+duv*Bq.w; e*=e1;
            }
        }
    } else {
        for (int l = 0; l < CL; l++) {
            const float4* dtv = (const float4*)(bc + (size_t)l*64);
            float dl  = dt_softplus(dtv, w, bias);
            float duv = dl * uptr[(size_t)l*DI];
            const float4* Bv = dtv + 4;
            #pragma unroll
            for (int q = 0; q < 4; q++) {
                float4 Bq = Bv[q];
                float e;
                e = ex2f(dl*a2[4*q+0]); p[4*q+0]*=e; s[4*q+0]=e*s[4*q+0]+duv*Bq.x;
                e = ex2f(dl*a2[4*q+1]); p[4*q+1]*=e; s[4*q+1]=e*s[4*q+1]+duv*Bq.y;
                e = ex2f(dl*a2[4*q+2]); p[4*q+2]*=e; s[4*q+2]=e*s[4*q+2]+duv*Bq.z;
                e = ex2f(dl*a2[4*q+3]); p[4*q+3]*=e; s[4*q+3]=e*s[4*q+3]+duv*Bq.w;
            }
        }
    }
    size_t o = (((size_t)b*NC + c)*DI + d)*DS;
    #pragma unroll
    for (int q = 0; q < 4; q++) {
        ((float4*)(ca + o))[q] = make_float4(p[4*q], p[4*q+1], p[4*q+2], p[4*q+3]);
        ((float4*)(cs + o))[q] = make_float4(s[4*q], s[4*q+1], s[4*q+2], s[4*q+3]);
    }
}

// ---------------- pass 2: combine chunk transitions -> h0 per chunk ----------------
__global__ void __launch_bounds__(DI)
scan_pass2(const float* __restrict__ ca, const float* __restrict__ cs,
           float* __restrict__ h0)
{
    int b = blockIdx.x, d = threadIdx.x;
    float h[DS];
    #pragma unroll
    for (int n = 0; n < DS; n++) h[n] = 0.f;
    for (int c = 0; c < NC; c++) {
        size_t o = (((size_t)b*NC + c)*DI + d)*DS;
        #pragma unroll
        for (int q = 0; q < 4; q++)
            ((float4*)(h0 + o))[q] = make_float4(h[4*q], h[4*q+1], h[4*q+2], h[4*q+3]);
        #pragma unroll
        for (int q = 0; q < 4; q++) {
            float4 pq = ((const float4*)(ca + o))[q];
            float4 sq = ((const float4*)(cs + o))[q];
            h[4*q+0] = pq.x*h[4*q+0] + sq.x;
            h[4*q+1] = pq.y*h[4*q+1] + sq.y;
            h[4*q+2] = pq.z*h[4*q+2] + sq.z;
            h[4*q+3] = pq.w*h[4*q+3] + sq.w;
        }
    }
}

// ---------------- pass 3: re-scan from h0, emit y = (scan + u*D) * silu(res) ----------------
__global__ void __launch_bounds__(128)
scan_pass3(const float* __restrict__ u,  const float* __restrict__ xr,
           const float* __restrict__ dbc, const float* __restrict__ Alog,
           const float* __restrict__ dtw, const float* __restrict__ dtb,
           const float* __restrict__ Dp,  const float* __restrict__ h0,
           float* __restrict__ y)
{
    int d = blockIdx.x * 128 + threadIdx.x;
    int c = blockIdx.y;
    int b = blockIdx.z;

    float a2[DS];
    #pragma unroll
    for (int n = 0; n < DS; n++) a2[n] = -__expf(Alog[d*DS + n]) * 1.44269504f;
    bool chain = true;
    #pragma unroll
    for (int n = 1; n < DS; n++)
        if (fabsf(a2[n] - (float)(n+1)*a2[0]) > 1e-4f*fabsf(a2[n])) chain = false;

    float w[DR];
    #pragma unroll
    for (int r = 0; r < DR; r++) w[r] = dtw[r*DI + d];
    float bias = dtb[d];
    float Dv = Dp[d];

    float h[DS];
    {
        size_t o = (((size_t)b*NC + c)*DI + d)*DS;
        #pragma unroll
        for (int q = 0; q < 4; q++) {
            float4 hq = ((const float4*)(h0 + o))[q];
            h[4*q] = hq.x; h[4*q+1] = hq.y; h[4*q+2] = hq.z; h[4*q+3] = hq.w;
        }
    }

    const float* bc   = dbc + ((size_t)b*SEQL + c*CL)*64;
    const float* uptr = u   + ((size_t)b*SEQL + c*CL)*DI + d;
    const float* rptr = xr  + ((size_t)b*SEQL + c*CL)*2*DI + DI + d;
    float*       yptr = y   + ((size_t)b*SEQL + c*CL)*DI + d;

    if (chain) {
        for (int l = 0; l < CL; l++) {
            const float4* dtv = (const float4*)(bc + (size_t)l*64);
            float dl  = dt_softplus(dtv, w, bias);
            float uv  = uptr[(size_t)l*DI];
            float duv = dl * uv;
            float res = rptr[(size_t)l*2*DI];
            const float4* Bv = dtv + 4;
            const float4* Cv = dtv + 8;
            float e1 = ex2f(dl*a2[0]);
            float e  = e1;
            float yv = 0.f;
            #pragma unroll
            for (int q = 0; q < 4; q++) {
                float4 Bq = Bv[q], Cq = Cv[q];
                h[4*q+0]=e*h[4*q+0]+duv*Bq.x; yv += h[4*q+0]*Cq.x; e*=e1;
                h[4*q+1]=e*h[4*q+1]+duv*Bq.y; yv += h[4*q+1]*Cq.y; e*=e1;
                h[4*q+2]=e*h[4*q+2]+duv*Bq.z; yv += h[4*q+2]*Cq.z; e*=e1;
                h[4*q+3]=e*h[4*q+3]+duv*Bq.w; yv += h[4*q+3]*Cq.w; e*=e1;
            }
            float o = yv + uv*Dv;
            o *= res / (1.f + __expf(-res));
            yptr[(size_t)l*DI] = o;
        }
    } else {
        for (int l = 0; l < CL; l++) {
            const float4* dtv = (const float4*)(bc + (size_t)l*64);
            float dl  = dt_softplus(dtv, w, bias);
            float uv  = uptr[(size_t)l*DI];
            float duv = dl * uv;
            float res = rptr[(size_t)l*2*DI];
            const float4* Bv = dtv + 4;
            const float4* Cv = dtv + 8;
            float yv = 0.f;
            #pragma unroll
            for (int q = 0; q < 4; q++) {
                float4 Bq = Bv[q], Cq = Cv[q];
                float e;
                e = ex2f(dl*a2[4*q+0]); h[4*q+0]=e*h[4*q+0]+duv*Bq.x; yv += h[4*q+0]*Cq.x;
                e = ex2f(dl*a2[4*q+1]); h[4*q+1]=e*h[4*q+1]+duv*Bq.y; yv += h[4*q+1]*Cq.y;
                e = ex2f(dl*a2[4*q+2]); h[4*q+2]=e*h[4*q+2]+duv*Bq.z; yv += h[4*q+2]*Cq.z;
                e = ex2f(dl*a2[4*q+3]); h[4*q+3]=e*h[4*q+3]+duv*Bq.w; yv += h[4*q+3]*Cq.w;
            }
            float o = yv + uv*Dv;
            o *= res / (1.f + __expf(-res));
            yptr[(size_t)l*DI] = o;
        }
    }
}

// ---------------- pad x_proj_w (L,512,48) -> (L,512,64) zero-padded ----------------
__global__ void pad_xpw_kernel(const float* __restrict__ xpw, float* __restrict__ out)
{
    int idx = blockIdx.x * 256 + threadIdx.x;
    int j  = idx & 63;
    int rk = idx >> 6;
    out[idx] = (j < 48) ? xpw[rk*48 + j] : 0.f;
}

// ---------------- deterministic two-stage mean over L ----------------
__global__ void mean_part_kernel(const float* __restrict__ seq, float* __restrict__ part)
{
    int b = blockIdx.x, c = blockIdx.y, e = threadIdx.x;
    const float* p = seq + ((size_t)b*SEQL + c*64)*DM + e;
    float s = 0.f;
    #pragma unroll 8
    for (int i = 0; i < 64; i++) s += p[(size_t)i*DM];
    part[(b*16 + c)*DM + e] = s;
}
__global__ void mean_final_kernel(const float* __restrict__ part, float* __restrict__ out)
{
    int b = blockIdx.x, e = threadIdx.x;
    float s = 0.f;
    #pragma unroll
    for (int c = 0; c < 16; c++) s += part[(b*16 + c)*DM + e];
    out[b*DM + e] = s * (1.f/1024.f);
}

// ---------------- launch ----------------
extern "C" void kernel_launch(void* const* d_in, const int* in_sizes, int n_in,
                              void* d_out, int out_size)
{
    const float* x    = (const float*)d_in[0];
    const float* plg  = (const float*)d_in[1];
    const float* plb  = (const float*)d_in[2];
    const float* ew   = (const float*)d_in[3];
    const float* eb   = (const float*)d_in[4];
    const float* elg  = (const float*)d_in[5];
    const float* elb  = (const float*)d_in[6];
    const float* rmsw = (const float*)d_in[7];
    const float* inw  = (const float*)d_in[8];
    const float* cw   = (const float*)d_in[9];
    const float* cb   = (const float*)d_in[10];
    const float* xpw  = (const float*)d_in[11];
    const float* dtw  = (const float*)d_in[12];
    const float* dtb  = (const float*)d_in[13];
    const float* Alog = (const float*)d_in[14];
    const float* Dpar = (const float*)d_in[15];
    const float* ow   = (const float*)d_in[16];

    float *seq, *xn, *xr, *u, *dbc, *y, *xpwp, *part, *ca, *cs, *h0;
    cudaGetSymbolAddress((void**)&seq,   g_seq);
    cudaGetSymbolAddress((void**)&xn,    g_xn);
    cudaGetSymbolAddress((void**)&xr,    g_xr);
    cudaGetSymbolAddress((void**)&u,     g_u);
    cudaGetSymbolAddress((void**)&dbc,   g_dbc);
    cudaGetSymbolAddress((void**)&y,     g_y);
    cudaGetSymbolAddress((void**)&xpwp,  g_xpw);
    cudaGetSymbolAddress((void**)&part,  g_part);
    cudaGetSymbolAddress((void**)&ca,    g_ca);
    cudaGetSymbolAddress((void**)&cs,    g_cs);
    cudaGetSymbolAddress((void**)&h0,    g_h0);

    const int M = BATCH * SEQL;  // 16384

    pad_xpw_kernel<<<512, 256>>>(xpw, xpwp);
    patch_embed_kernel<<<2048, 256>>>(x, plg, plb, ew, eb, elg, elb, seq);

    for (int L = 0; L < NL; L++) {
        rmsnorm_kernel<<<2048, 256>>>(seq, rmsw + L*DM, xn);

        // in_proj: (16384,256) @ (256,1024) — TF32 tensor cores
        gemm_tf32<false><<<dim3(1024/64, M/128), 256>>>(
            xn, inw + (size_t)L*DM*2*DI, xr, M, 2*DI, DM);

        conv_silu_kernel<<<dim3(2,16,16), 256>>>(xr, cw + L*DI*4, cb + L*DI, u);

        // x_proj: (16384,512) @ (512,64pad) — exact fp32 (feeds recurrence)
        gemm_kernel<64,64,16,4,4,false><<<dim3(1, M/64), 256>>>(
            u, xpwp + (size_t)L*DI*64, dbc, M, 64, DI);

        scan_pass1<<<dim3(4, NC, BATCH), 128>>>(u, dbc, Alog + L*DI*DS,
                                                dtw + L*DR*DI, dtb + L*DI, ca, cs);
        scan_pass2<<<BATCH, DI>>>(ca, cs, h0);
        scan_pass3<<<dim3(4, NC, BATCH), 128>>>(u, xr, dbc, Alog + L*DI*DS,
                                                dtw + L*DR*DI, dtb + L*DI,
                                                Dpar + L*DI, h0, y);

        // out_proj (+residual into seq): (16384,512) @ (512,256) — TF32 tensor cores
        gemm_tf32<true><<<dim3(DM/64, M/128), 256>>>(
            y, ow + (size_t)L*DI*DM, seq, M, DM, DI);
    }

    mean_part_kernel<<<dim3(16,16), 256>>>(seq, part);
    mean_final_kernel<<<16, 256>>>(part, (float*)d_out);
}

// round 4
// speedup vs baseline: 4.6034x; 1.1436x over previous
#include <cuda_runtime.h>
#include <math.h>

#define BATCH 16
#define SEQL  1024
#define DM    256
#define DI    512
#define DS    16
#define DR    16
#define NL    4
#define NC    16        // scan chunks
#define CL    (SEQL/NC) // 64 steps per chunk

// ---------------- scratch (static device globals; no allocation) ----------------
__device__ float g_seq  [BATCH*SEQL*DM];
__device__ float g_xn   [BATCH*SEQL*DM];
__device__ float g_xr   [BATCH*SEQL*2*DI];
__device__ float g_u    [BATCH*SEQL*DI];
__device__ float g_dbc  [BATCH*SEQL*64];
__device__ float g_y    [BATCH*SEQL*DI];
__device__ float g_xpw  [NL*DI*64];
__device__ float g_part [BATCH*16*DM];
__device__ float g_ca   [BATCH*NC*DI*DS];
__device__ float g_cs   [BATCH*NC*DI*DS];
__device__ float g_h0   [BATCH*NC*DI*DS];

__device__ __forceinline__ float ex2f(float x) {
    float r; asm("ex2.approx.f32 %0, %1;" : "=f"(r) : "f"(x)); return r;
}
__device__ __forceinline__ unsigned f2tf32(float f) {
    unsigned r; asm("cvt.rna.tf32.f32 %0, %1;" : "=r"(r) : "f"(f)); return r;
}

// ---------------- patch extract + LN(48) + embed(48->256) + LN(256) ----------------
__global__ void patch_embed_kernel(const float* __restrict__ x,
                                   const float* __restrict__ plg, const float* __restrict__ plb,
                                   const float* __restrict__ ew,  const float* __restrict__ eb,
                                   const float* __restrict__ elg, const float* __restrict__ elb,
                                   float* __restrict__ seq)
{
    __shared__ float sp[8][48];
    int warp = threadIdx.x >> 5, lane = threadIdx.x & 31;
    int t = blockIdx.x * 8 + warp;
    int b = t >> 10, pos = t & 1023;
    int hy = pos >> 5, wx = pos & 31;

    float p1, p2 = 0.f;
    {
        int j = lane;
        int c = j >> 4, py = (j >> 2) & 3, px = j & 3;
        p1 = x[((b*3 + c)*128 + hy*4 + py)*128 + wx*4 + px];
        if (lane < 16) {
            j = 32 + lane;
            c = j >> 4; py = (j >> 2) & 3; px = j & 3;
            p2 = x[((b*3 + c)*128 + hy*4 + py)*128 + wx*4 + px];
        }
    }
    float s = p1 + p2, ss = p1*p1 + p2*p2;
    #pragma unroll
    for (int o = 16; o > 0; o >>= 1) {
        s  += __shfl_xor_sync(0xffffffffu, s,  o);
        ss += __shfl_xor_sync(0xffffffffu, ss, o);
    }
    float mu  = s * (1.f/48.f);
    float var = ss * (1.f/48.f) - mu*mu;
    float rs  = rsqrtf(var + 1e-5f);
    sp[warp][lane] = (p1 - mu)*rs*plg[lane] + plb[lane];
    if (lane < 16) sp[warp][32+lane] = (p2 - mu)*rs*plg[32+lane] + plb[32+lane];
    __syncwarp();

    float acc[8];
    #pragma unroll
    for (int i = 0; i < 8; i++) acc[i] = eb[lane + 32*i];
    #pragma unroll 4
    for (int j = 0; j < 48; j++) {
        float v = sp[warp][j];
        const float* w = ew + j*DM + lane;
        #pragma unroll
        for (int i = 0; i < 8; i++) acc[i] += v * w[32*i];
    }
    float s2 = 0.f, ss2 = 0.f;
    #pragma unroll
    for (int i = 0; i < 8; i++) { s2 += acc[i]; ss2 += acc[i]*acc[i]; }
    #pragma unroll
    for (int o = 16; o > 0; o >>= 1) {
        s2  += __shfl_xor_sync(0xffffffffu, s2,  o);
        ss2 += __shfl_xor_sync(0xffffffffu, ss2, o);
    }
    float mu2  = s2 * (1.f/256.f);
    float var2 = ss2 * (1.f/256.f) - mu2*mu2;
    float rs2  = rsqrtf(var2 + 1e-5f);
    #pragma unroll
    for (int i = 0; i < 8; i++) {
        int e = lane + 32*i;
        seq[(size_t)t*DM + e] = (acc[i] - mu2)*rs2*elg[e] + elb[e];
    }
}

// ---------------- rmsnorm over DM=256 (warp per token) ----------------
__global__ void rmsnorm_kernel(const float* __restrict__ in, const float* __restrict__ w,
                               float* __restrict__ out)
{
    int warp = threadIdx.x >> 5, lane = threadIdx.x & 31;
    int t = blockIdx.x * 8 + warp;
    const float4* ip = (const float4*)(in + (size_t)t*DM);
    float4 v0 = ip[lane], v1 = ip[lane+32];
    float ss = v0.x*v0.x+v0.y*v0.y+v0.z*v0.z+v0.w*v0.w
             + v1.x*v1.x+v1.y*v1.y+v1.z*v1.z+v1.w*v1.w;
    #pragma unroll
    for (int o = 16; o > 0; o >>= 1) ss += __shfl_xor_sync(0xffffffffu, ss, o);
    float sc = rsqrtf(ss*(1.f/256.f) + 1e-5f);
    const float4* wp = (const float4*)w;
    float4 w0 = wp[lane], w1 = wp[lane+32];
    float4 o0 = make_float4(v0.x*sc*w0.x, v0.y*sc*w0.y, v0.z*sc*w0.z, v0.w*sc*w0.w);
    float4 o1 = make_float4(v1.x*sc*w1.x, v1.y*sc*w1.y, v1.z*sc*w1.z, v1.w*sc*w1.w);
    float4* op = (float4*)(out + (size_t)t*DM);
    op[lane] = o0; op[lane+32] = o1;
}

// ---------------- TF32 tensor-core GEMM, fragment-order smem ----------------
// BM=128, BN=64, BK=32, 256 threads (8 warps: 4 in M x 2 in N), warp tile 32x32.
// Smem is laid out so each thread's mma fragment is one contiguous 16B word:
//   A: As2[(kc*8 + m16)*128 + kc*4 + lane*4 + reg], reg = hi + 2*khi
//   B: Bs2[(kc*4 + pair)*128 + kc*4 + lane*4 + odd*2 + khi]
template<bool RESID>
__global__ void __launch_bounds__(256, 2)
gemm_tf32(const float* __restrict__ A, const float* __restrict__ Bm,
          float* __restrict__ C, int M, int N, int K)
{
    __shared__ __align__(16) unsigned As2[4*8*128 + 16];
    __shared__ __align__(16) unsigned Bs2[4*4*128 + 16];
    const int tid  = threadIdx.x;
    const int m0   = blockIdx.y * 128;
    const int n0   = blockIdx.x * 64;
    const int warp = tid >> 5, lane = tid & 31;
    const int g = lane >> 2, t = lane & 3;
    const int wmt   = (warp & 3) * 2;   // m16-tile base (2 per warp)
    const int wpair = (warp >> 2) * 2;  // B pair base (2 per warp)
    const int wn    = (warp >> 2) * 32;
    const int wm    = (warp & 3) * 32;

    // gmem coords
    const int rowa = tid >> 3, cva = tid & 7;    // A: rows rowa+it*32, k = cva*4
    const int rowb = tid >> 4, cvb = tid & 15;   // B: rows rowb+it*16, n = cvb*4
    const float* Aptr = A + (size_t)(m0 + rowa)*K + cva*4;
    const float* Bptr = Bm + (size_t)rowb*N + n0 + cvb*4;

    // store-offset constants
    const int kca = cva >> 1, khia = cva & 1;
    const int pairb = cvb >> 2, oddb = (cvb >> 1) & 1, glob = cvb & 1;

    float acc[2][4][4];
    #pragma unroll
    for (int a = 0; a < 2; a++)
        #pragma unroll
        for (int b = 0; b < 4; b++)
            #pragma unroll
            for (int c = 0; c < 4; c++) acc[a][b][c] = 0.f;

    float4 ra[4], rb[2];
    #pragma unroll
    for (int it = 0; it < 4; it++) ra[it] = *(const float4*)(Aptr + (size_t)it*32*K);
    #pragma unroll
    for (int it = 0; it < 2; it++) rb[it] = *(const float4*)(Bptr + (size_t)it*16*N);

    for (int k0 = 0; k0 < K; k0 += 32) {
        // ---- store regs -> fragment-order smem (with tf32 convert) ----
        #pragma unroll
        for (int it = 0; it < 4; it++) {
            int row = rowa + it*32;
            int m16 = row >> 4, r = row & 15;
            int rlow = r & 7, hi = (r >> 3) & 1;
            int off = (kca*8 + m16)*128 + kca*4 + rlow*16 + hi + 2*khia;
            As2[off+0]  = f2tf32(ra[it].x);
            As2[off+4]  = f2tf32(ra[it].y);
            As2[off+8]  = f2tf32(ra[it].z);
            As2[off+12] = f2tf32(ra[it].w);
        }
        #pragma unroll
        for (int it = 0; it < 2; it++) {
            int row = rowb + it*16;
            int kc = row >> 3, kl = row & 7;
            int tt = kl & 3, khi = kl >> 2;
            int off = (kc*4 + pairb)*128 + kc*4 + (glob*16 + tt)*4 + oddb*2 + khi;
            Bs2[off+0]  = f2tf32(rb[it].x);
            Bs2[off+16] = f2tf32(rb[it].y);
            Bs2[off+32] = f2tf32(rb[it].z);
            Bs2[off+48] = f2tf32(rb[it].w);
        }
        __syncthreads();

        // ---- prefetch next gmem tile into regs ----
        if (k0 + 32 < K) {
            #pragma unroll
            for (int it = 0; it < 4; it++)
                ra[it] = *(const float4*)(Aptr + (size_t)it*32*K + k0 + 32);
            #pragma unroll
            for (int it = 0; it < 2; it++)
                rb[it] = *(const float4*)(Bptr + (size_t)(k0 + 32 + it*16)*N);
        }

        // ---- compute: 4 kc-steps, LDS.128 fragment loads ----
        #pragma unroll
        for (int kc = 0; kc < 4; kc++) {
            uint4 a0 = *(const uint4*)&As2[(kc*8 + wmt + 0)*128 + kc*4 + lane*4];
            uint4 a1 = *(const uint4*)&As2[(kc*8 + wmt + 1)*128 + kc*4 + lane*4];
            uint4 b0 = *(const uint4*)&Bs2[(kc*4 + wpair + 0)*128 + kc*4 + lane*4];
            uint4 b1 = *(const uint4*)&Bs2[(kc*4 + wpair + 1)*128 + kc*4 + lane*4];
            unsigned af[2][4] = {{a0.x, a0.y, a0.z, a0.w}, {a1.x, a1.y, a1.z, a1.w}};
            unsigned bf[4][2] = {{b0.x, b0.y}, {b0.z, b0.w}, {b1.x, b1.y}, {b1.z, b1.w}};
            #pragma unroll
            for (int mt = 0; mt < 2; mt++)
                #pragma unroll
                for (int nt = 0; nt < 4; nt++) {
                    asm volatile(
                        "mma.sync.aligned.m16n8k8.row.col.f32.tf32.tf32.f32 "
                        "{%0,%1,%2,%3},{%4,%5,%6,%7},{%8,%9},{%0,%1,%2,%3};"
                        : "+f"(acc[mt][nt][0]), "+f"(acc[mt][nt][1]),
                          "+f"(acc[mt][nt][2]), "+f"(acc[mt][nt][3])
                        : "r"(af[mt][0]), "r"(af[mt][1]), "r"(af[mt][2]), "r"(af[mt][3]),
                          "r"(bf[nt][0]), "r"(bf[nt][1]));
                }
        }
        __syncthreads();
    }

    #pragma unroll
    for (int mt = 0; mt < 2; mt++)
        #pragma unroll
        for (int nt = 0; nt < 4; nt++) {
            int row = m0 + wm + mt*16 + g;
            int col = n0 + wn + nt*8 + 2*t;
            float* p0 = C + (size_t)row*N + col;
            float* p1 = C + (size_t)(row+8)*N + col;
            float2 v0 = make_float2(acc[mt][nt][0], acc[mt][nt][1]);
            float2 v1 = make_float2(acc[mt][nt][2], acc[mt][nt][3]);
            if (RESID) {
                float2 c0 = *(const float2*)p0, c1 = *(const float2*)p1;
                v0.x += c0.x; v0.y += c0.y; v1.x += c1.x; v1.y += c1.y;
            }
            *(float2*)p0 = v0;
            *(float2*)p1 = v1;
        }
}

// ---------------- depthwise causal conv(4) + SiLU ----------------
__global__ void conv_silu_kernel(const float* __restrict__ xr, const float* __restrict__ cw,
                                 const float* __restrict__ cb, float* __restrict__ u)
{
    int d  = blockIdx.x * 256 + threadIdx.x;
    int l0 = blockIdx.y * 64;
    int b  = blockIdx.z;
    float4 w   = *(const float4*)(cw + d*4);
    float bias = cb[d];
    const float* xs = xr + ((size_t)b*SEQL)*(2*DI) + d;
    float h0 = (l0 >= 3) ? xs[(size_t)(l0-3)*(2*DI)] : 0.f;
    float h1 = (l0 >= 2) ? xs[(size_t)(l0-2)*(2*DI)] : 0.f;
    float h2 = (l0 >= 1) ? xs[(size_t)(l0-1)*(2*DI)] : 0.f;
    float* up = u + ((size_t)b*SEQL + l0)*DI + d;
    #pragma unroll 4
    for (int i = 0; i < 64; i++) {
        float cur = xs[(size_t)(l0+i)*(2*DI)];
        float z = bias + w.x*h0 + w.y*h1 + w.z*h2 + w.w*cur;
        up[(size_t)i*DI] = z / (1.f + __expf(-z));
        h0 = h1; h1 = h2; h2 = cur;
    }
}

// ---- dt_proj + softplus fused inline ----
__device__ __forceinline__ float dt_softplus(const float4* dtv, const float* w, float bias)
{
    float4 t0 = dtv[0], t1 = dtv[1], t2 = dtv[2], t3 = dtv[3];
    float acc = bias;
    acc += t0.x*w[0]  + t0.y*w[1]  + t0.z*w[2]  + t0.w*w[3];
    acc += t1.x*w[4]  + t1.y*w[5]  + t1.z*w[6]  + t1.w*w[7];
    acc += t2.x*w[8]  + t2.y*w[9]  + t2.z*w[10] + t2.w*w[11];
    acc += t3.x*w[12] + t3.y*w[13] + t3.z*w[14] + t3.w*w[15];
    return (acc > 15.f) ? acc : log1pf(__expf(acc));
}

// ---------------- chunked scan pass 1: local cumA + local state ----------------
__global__ void __launch_bounds__(128)
scan_pass1(const float* __restrict__ u,  const float* __restrict__ dbc,
           const float* __restrict__ Alog, const float* __restrict__ dtw,
           const float* __restrict__ dtb,
           float* __restrict__ ca, float* __restrict__ cs)
{
    int d = blockIdx.x * 128 + threadIdx.x;
    int c = blockIdx.y;
    int b = blockIdx.z;

    float a2[DS];
    #pragma unroll
    for (int n = 0; n < DS; n++) a2[n] = -__expf(Alog[d*DS + n]) * 1.44269504f;
    bool chain = true;
    #pragma unroll
    for (int n = 1; n < DS; n++)
        if (fabsf(a2[n] - (float)(n+1)*a2[0]) > 1e-4f*fabsf(a2[n])) chain = false;

    float w[DR];
    #pragma unroll
    for (int r = 0; r < DR; r++) w[r] = dtw[r*DI + d];
    float bias = dtb[d];

    float p[DS], s[DS];
    #pragma unroll
    for (int n = 0; n < DS; n++) { p[n] = 1.f; s[n] = 0.f; }

    const float* bc   = dbc + ((size_t)b*SEQL + c*CL)*64;
    const float* uptr = u   + ((size_t)b*SEQL + c*CL)*DI + d;

    if (chain) {
        for (int l = 0; l < CL; l++) {
            const float4* dtv = (const float4*)(bc + (size_t)l*64);
            float dl  = dt_softplus(dtv, w, bias);
            float duv = dl * uptr[(size_t)l*DI];
            const float4* Bv = dtv + 4;
            float e1 = ex2f(dl*a2[0]);
            float e  = e1;
            #pragma unroll
            for (int q = 0; q < 4; q++) {
                float4 Bq = Bv[q];
                p[4*q+0]*=e; s[4*q+0]=e*s[4*q+0]+duv*Bq.x; e*=e1;
                p[4*q+1]*=e; s[4*q+1]=e*s[4*q+1]+duv*Bq.y; e*=e1;
                p[4*q+2]*=e; s[4*q+2]=e*s[4*q+2]+duv*Bq.z; e*=e1;
                p[4*q+3]*=e; s[4*q+3]=e*s[4*q+3]+duv*Bq.w; e*=e1;
            }
        }
    } else {
        for (int l = 0; l < CL; l++) {
            const float4* dtv = (const float4*)(bc + (size_t)l*64);
            float dl  = dt_softplus(dtv, w, bias);
            float duv = dl * uptr[(size_t)l*DI];
            const float4* Bv = dtv + 4;
            #pragma unroll
            for (int q = 0; q < 4; q++) {
                float4 Bq = Bv[q];
                float e;
                e = ex2f(dl*a2[4*q+0]); p[4*q+0]*=e; s[4*q+0]=e*s[4*q+0]+duv*Bq.x;
                e = ex2f(dl*a2[4*q+1]); p[4*q+1]*=e; s[4*q+1]=e*s[4*q+1]+duv*Bq.y;
                e = ex2f(dl*a2[4*q+2]); p[4*q+2]*=e; s[4*q+2]=e*s[4*q+2]+duv*Bq.z;
                e = ex2f(dl*a2[4*q+3]); p[4*q+3]*=e; s[4*q+3]=e*s[4*q+3]+duv*Bq.w;
            }
        }
    }
    size_t o = (((size_t)b*NC + c)*DI + d)*DS;
    #pragma unroll
    for (int q = 0; q < 4; q++) {
        ((float4*)(ca + o))[q] = make_float4(p[4*q], p[4*q+1], p[4*q+2], p[4*q+3]);
        ((float4*)(cs + o))[q] = make_float4(s[4*q], s[4*q+1], s[4*q+2], s[4*q+3]);
    }
}

// ---------------- pass 2: combine chunk transitions -> h0 per chunk ----------------
__global__ void __launch_bounds__(DI)
scan_pass2(const float* __restrict__ ca, const float* __restrict__ cs,
           float* __restrict__ h0)
{
    int b = blockIdx.x, d = threadIdx.x;
    float h[DS];
    #pragma unroll
    for (int n = 0; n < DS; n++) h[n] = 0.f;
    for (int c = 0; c < NC; c++) {
        size_t o = (((size_t)b*NC + c)*DI + d)*DS;
        #pragma unroll
        for (int q = 0; q < 4; q++)
            ((float4*)(h0 + o))[q] = make_float4(h[4*q], h[4*q+1], h[4*q+2], h[4*q+3]);
        #pragma unroll
        for (int q = 0; q < 4; q++) {
            float4 pq = ((const float4*)(ca + o))[q];
            float4 sq = ((const float4*)(cs + o))[q];
            h[4*q+0] = pq.x*h[4*q+0] + sq.x;
            h[4*q+1] = pq.y*h[4*q+1] + sq.y;
            h[4*q+2] = pq.z*h[4*q+2] + sq.z;
            h[4*q+3] = pq.w*h[4*q+3] + sq.w;
        }
    }
}

// ---------------- pass 3: re-scan from h0, emit y = (scan + u*D) * silu(res) ----------------
__global__ void __launch_bounds__(128)
scan_pass3(const float* __restrict__ u,  const float* __restrict__ xr,
           const float* __restrict__ dbc, const float* __restrict__ Alog,
           const float* __restrict__ dtw, const float* __restrict__ dtb,
           const float* __restrict__ Dp,  const float* __restrict__ h0,
           float* __restrict__ y)
{
    int d = blockIdx.x * 128 + threadIdx.x;
    int c = blockIdx.y;
    int b = blockIdx.z;

    float a2[DS];
    #pragma unroll
    for (int n = 0; n < DS; n++) a2[n] = -__expf(Alog[d*DS + n]) * 1.44269504f;
    bool chain = true;
    #pragma unroll
    for (int n = 1; n < DS; n++)
        if (fabsf(a2[n] - (float)(n+1)*a2[0]) > 1e-4f*fabsf(a2[n])) chain = false;

    float w[DR];
    #pragma unroll
    for (int r = 0; r < DR; r++) w[r] = dtw[r*DI + d];
    float bias = dtb[d];
    float Dv = Dp[d];

    float h[DS];
    {
        size_t o = (((size_t)b*NC + c)*DI + d)*DS;
        #pragma unroll
        for (int q = 0; q < 4; q++) {
            float4 hq = ((const float4*)(h0 + o))[q];
            h[4*q] = hq.x; h[4*q+1] = hq.y; h[4*q+2] = hq.z; h[4*q+3] = hq.w;
        }
    }

    const float* bc   = dbc + ((size_t)b*SEQL + c*CL)*64;
    const float* uptr = u   + ((size_t)b*SEQL + c*CL)*DI + d;
    const float* rptr = xr  + ((size_t)b*SEQL + c*CL)*2*DI + DI + d;
    float*       yptr = y   + ((size_t)b*SEQL + c*CL)*DI + d;

    if (chain) {
        for (int l = 0; l < CL; l++) {
            const float4* dtv = (const float4*)(bc + (size_t)l*64);
            float dl  = dt_softplus(dtv, w, bias);
            float uv  = uptr[(size_t)l*DI];
            float duv = dl * uv;
            float res = rptr[(size_t)l*2*DI];
            const float4* Bv = dtv + 4;
            const float4* Cv = dtv + 8;
            float e1 = ex2f(dl*a2[0]);
            float e  = e1;
            float yv = 0.f;
            #pragma unroll
            for (int q = 0; q < 4; q++) {
                float4 Bq = Bv[q], Cq = Cv[q];
                h[4*q+0]=e*h[4*q+0]+duv*Bq.x; yv += h[4*q+0]*Cq.x; e*=e1;
                h[4*q+1]=e*h[4*q+1]+duv*Bq.y; yv += h[4*q+1]*Cq.y; e*=e1;
                h[4*q+2]=e*h[4*q+2]+duv*Bq.z; yv += h[4*q+2]*Cq.z; e*=e1;
                h[4*q+3]=e*h[4*q+3]+duv*Bq.w; yv += h[4*q+3]*Cq.w; e*=e1;
            }
            float o = yv + uv*Dv;
            o *= res / (1.f + __expf(-res));
            yptr[(size_t)l*DI] = o;
        }
    } else {
        for (int l = 0; l < CL; l++) {
            const float4* dtv = (const float4*)(bc + (size_t)l*64);
            float dl  = dt_softplus(dtv, w, bias);
            float uv  = uptr[(size_t)l*DI];
            float duv = dl * uv;
            float res = rptr[(size_t)l*2*DI];
            const float4* Bv = dtv + 4;
            const float4* Cv = dtv + 8;
            float yv = 0.f;
            #pragma unroll
            for (int q = 0; q < 4; q++) {
                float4 Bq = Bv[q], Cq = Cv[q];
                float e;
                e = ex2f(dl*a2[4*q+0]); h[4*q+0]=e*h[4*q+0]+duv*Bq.x; yv += h[4*q+0]*Cq.x;
                e = ex2f(dl*a2[4*q+1]); h[4*q+1]=e*h[4*q+1]+duv*Bq.y; yv += h[4*q+1]*Cq.y;
                e = ex2f(dl*a2[4*q+2]); h[4*q+2]=e*h[4*q+2]+duv*Bq.z; yv += h[4*q+2]*Cq.z;
                e = ex2f(dl*a2[4*q+3]); h[4*q+3]=e*h[4*q+3]+duv*Bq.w; yv += h[4*q+3]*Cq.w;
            }
            float o = yv + uv*Dv;
            o *= res / (1.f + __expf(-res));
            yptr[(size_t)l*DI] = o;
        }
    }
}

// ---------------- pad x_proj_w (L,512,48) -> (L,512,64) zero-padded ----------------
__global__ void pad_xpw_kernel(const float* __restrict__ xpw, float* __restrict__ out)
{
    int idx = blockIdx.x * 256 + threadIdx.x;
    int j  = idx & 63;
    int rk = idx >> 6;
    out[idx] = (j < 48) ? xpw[rk*48 + j] : 0.f;
}

// ---------------- deterministic two-stage mean over L ----------------
__global__ void mean_part_kernel(const float* __restrict__ seq, float* __restrict__ part)
{
    int b = blockIdx.x, c = blockIdx.y, e = threadIdx.x;
    const float* p = seq + ((size_t)b*SEQL + c*64)*DM + e;
    float s = 0.f;
    #pragma unroll 8
    for (int i = 0; i < 64; i++) s += p[(size_t)i*DM];
    part[(b*16 + c)*DM + e] = s;
}
__global__ void mean_final_kernel(const float* __restrict__ part, float* __restrict__ out)
{
    int b = blockIdx.x, e = threadIdx.x;
    float s = 0.f;
    #pragma unroll
    for (int c = 0; c < 16; c++) s += part[(b*16 + c)*DM + e];
    out[b*DM + e] = s * (1.f/1024.f);
}

// ---------------- launch ----------------
extern "C" void kernel_launch(void* const* d_in, const int* in_sizes, int n_in,
                              void* d_out, int out_size)
{
    const float* x    = (const float*)d_in[0];
    const float* plg  = (const float*)d_in[1];
    const float* plb  = (const float*)d_in[2];
    const float* ew   = (const float*)d_in[3];
    const float* eb   = (const float*)d_in[4];
    const float* elg  = (const float*)d_in[5];
    const float* elb  = (const float*)d_in[6];
    const float* rmsw = (const float*)d_in[7];
    const float* inw  = (const float*)d_in[8];
    const float* cw   = (const float*)d_in[9];
    const float* cb   = (const float*)d_in[10];
    const float* xpw  = (const float*)d_in[11];
    const float* dtw  = (const float*)d_in[12];
    const float* dtb  = (const float*)d_in[13];
    const float* Alog = (const float*)d_in[14];
    const float* Dpar = (const float*)d_in[15];
    const float* ow   = (const float*)d_in[16];

    float *seq, *xn, *xr, *u, *dbc, *y, *xpwp, *part, *ca, *cs, *h0;
    cudaGetSymbolAddress((void**)&seq,   g_seq);
    cudaGetSymbolAddress((void**)&xn,    g_xn);
    cudaGetSymbolAddress((void**)&xr,    g_xr);
    cudaGetSymbolAddress((void**)&u,     g_u);
    cudaGetSymbolAddress((void**)&dbc,   g_dbc);
    cudaGetSymbolAddress((void**)&y,     g_y);
    cudaGetSymbolAddress((void**)&xpwp,  g_xpw);
    cudaGetSymbolAddress((void**)&part,  g_part);
    cudaGetSymbolAddress((void**)&ca,    g_ca);
    cudaGetSymbolAddress((void**)&cs,    g_cs);
    cudaGetSymbolAddress((void**)&h0,    g_h0);

    const int M = BATCH * SEQL;  // 16384

    pad_xpw_kernel<<<512, 256>>>(xpw, xpwp);
    patch_embed_kernel<<<2048, 256>>>(x, plg, plb, ew, eb, elg, elb, seq);

    for (int L = 0; L < NL; L++) {
        rmsnorm_kernel<<<2048, 256>>>(seq, rmsw + L*DM, xn);

        // in_proj: (16384,256) @ (256,1024) — TF32 tensor cores
        gemm_tf32<false><<<dim3(16, 128), 256>>>(
            xn, inw + (size_t)L*DM*2*DI, xr, M, 2*DI, DM);

        conv_silu_kernel<<<dim3(2,16,16), 256>>>(xr, cw + L*DI*4, cb + L*DI, u);

        // x_proj: (16384,512) @ (512,64pad) — TF32 tensor cores
        gemm_tf32<false><<<dim3(1, 128), 256>>>(
            u, xpwp + (size_t)L*DI*64, dbc, M, 64, DI);

        scan_pass1<<<dim3(4, NC, BATCH), 128>>>(u, dbc, Alog + L*DI*DS,
                                                dtw + L*DR*DI, dtb + L*DI, ca, cs);
        scan_pass2<<<BATCH, DI>>>(ca, cs, h0);
        scan_pass3<<<dim3(4, NC, BATCH), 128>>>(u, xr, dbc, Alog + L*DI*DS,
                                                dtw + L*DR*DI, dtb + L*DI,
                                                Dpar + L*DI, h0, y);

        // out_proj (+residual into seq): (16384,512) @ (512,256) — TF32 tensor cores
        gemm_tf32<true><<<dim3(4, 128), 256>>>(
            y, ow + (size_t)L*DI*DM, seq, M, DM, DI);
    }

    mean_part_kernel<<<dim3(16,16), 256>>>(seq, part);
    mean_final_kernel<<<16, 256>>>(part, (float*)d_out);
}

// round 5
// speedup vs baseline: 5.7216x; 1.2429x over previous
#include <cuda_runtime.h>
#include <cuda_bf16.h>
#include <math.h>

#define BATCH 16
#define SEQL  1024
#define DM    256
#define DI    512
#define DS    16
#define DR    16
#define NL    4
#define NC    16        // scan chunks
#define CL    (SEQL/NC) // 64 steps per chunk

// ---------------- scratch (static device globals; no allocation) ----------------
__device__ float g_seq  [BATCH*SEQL*DM];
__device__ float g_xn   [BATCH*SEQL*DM];
__device__ float g_xr   [BATCH*SEQL*2*DI];
__device__ float g_u    [BATCH*SEQL*DI];
__device__ float g_dbc  [BATCH*SEQL*64];
__device__ float g_y    [BATCH*SEQL*DI];
__device__ float g_xpw  [NL*DI*64];
__device__ float g_part [BATCH*16*DM];
__device__ float g_ca   [BATCH*NC*DI*DS];
__device__ float g_cs   [BATCH*NC*DI*DS];
__device__ float g_h0   [BATCH*NC*DI*DS];

__device__ __forceinline__ float ex2f(float x) {
    float r; asm("ex2.approx.f32 %0, %1;" : "=f"(r) : "f"(x)); return r;
}
__device__ __forceinline__ float lg2f(float x) {
    float r; asm("lg2.approx.f32 %0, %1;" : "=f"(r) : "f"(x)); return r;
}
// softplus via 2 MUFU ops (exact passthrough for large x)
__device__ __forceinline__ float softplus_f(float x) {
    float t = ex2f(x * 1.44269504f);
    return (x > 15.f) ? x : 0.69314718f * lg2f(1.f + t);
}

// ---------------- patch extract + LN(48) + embed(48->256) + LN(256) ----------------
__global__ void patch_embed_kernel(const float* __restrict__ x,
                                   const float* __restrict__ plg, const float* __restrict__ plb,
                                   const float* __restrict__ ew,  const float* __restrict__ eb,
                                   const float* __restrict__ elg, const float* __restrict__ elb,
                                   float* __restrict__ seq)
{
    __shared__ float sp[8][48];
    int warp = threadIdx.x >> 5, lane = threadIdx.x & 31;
    int t = blockIdx.x * 8 + warp;
    int b = t >> 10, pos = t & 1023;
    int hy = pos >> 5, wx = pos & 31;

    float p1, p2 = 0.f;
    {
        int j = lane;
        int c = j >> 4, py = (j >> 2) & 3, px = j & 3;
        p1 = x[((b*3 + c)*128 + hy*4 + py)*128 + wx*4 + px];
        if (lane < 16) {
            j = 32 + lane;
            c = j >> 4; py = (j >> 2) & 3; px = j & 3;
            p2 = x[((b*3 + c)*128 + hy*4 + py)*128 + wx*4 + px];
        }
    }
    float s = p1 + p2, ss = p1*p1 + p2*p2;
    #pragma unroll
    for (int o = 16; o > 0; o >>= 1) {
        s  += __shfl_xor_sync(0xffffffffu, s,  o);
        ss += __shfl_xor_sync(0xffffffffu, ss, o);
    }
    float mu  = s * (1.f/48.f);
    float var = ss * (1.f/48.f) - mu*mu;
    float rs  = rsqrtf(var + 1e-5f);
    sp[warp][lane] = (p1 - mu)*rs*plg[lane] + plb[lane];
    if (lane < 16) sp[warp][32+lane] = (p2 - mu)*rs*plg[32+lane] + plb[32+lane];
    __syncwarp();

    float acc[8];
    #pragma unroll
    for (int i = 0; i < 8; i++) acc[i] = eb[lane + 32*i];
    #pragma unroll 4
    for (int j = 0; j < 48; j++) {
        float v = sp[warp][j];
        const float* w = ew + j*DM + lane;
        #pragma unroll
        for (int i = 0; i < 8; i++) acc[i] += v * w[32*i];
    }
    float s2 = 0.f, ss2 = 0.f;
    #pragma unroll
    for (int i = 0; i < 8; i++) { s2 += acc[i]; ss2 += acc[i]*acc[i]; }
    #pragma unroll
    for (int o = 16; o > 0; o >>= 1) {
        s2  += __shfl_xor_sync(0xffffffffu, s2,  o);
        ss2 += __shfl_xor_sync(0xffffffffu, ss2, o);
    }
    float mu2  = s2 * (1.f/256.f);
    float var2 = ss2 * (1.f/256.f) - mu2*mu2;
    float rs2  = rsqrtf(var2 + 1e-5f);
    #pragma unroll
    for (int i = 0; i < 8; i++) {
        int e = lane + 32*i;
        seq[(size_t)t*DM + e] = (acc[i] - mu2)*rs2*elg[e] + elb[e];
    }
}

// ---------------- rmsnorm over DM=256 (warp per token) ----------------
__global__ void rmsnorm_kernel(const float* __restrict__ in, const float* __restrict__ w,
                               float* __restrict__ out)
{
    int warp = threadIdx.x >> 5, lane = threadIdx.x & 31;
    int t = blockIdx.x * 8 + warp;
    const float4* ip = (const float4*)(in + (size_t)t*DM);
    float4 v0 = ip[lane], v1 = ip[lane+32];
    float ss = v0.x*v0.x+v0.y*v0.y+v0.z*v0.z+v0.w*v0.w
             + v1.x*v1.x+v1.y*v1.y+v1.z*v1.z+v1.w*v1.w;
    #pragma unroll
    for (int o = 16; o > 0; o >>= 1) ss += __shfl_xor_sync(0xffffffffu, ss, o);
    float sc = rsqrtf(ss*(1.f/256.f) + 1e-5f);
    const float4* wp = (const float4*)w;
    float4 w0 = wp[lane], w1 = wp[lane+32];
    float4 o0 = make_float4(v0.x*sc*w0.x, v0.y*sc*w0.y, v0.z*sc*w0.z, v0.w*sc*w0.w);
    float4 o1 = make_float4(v1.x*sc*w1.x, v1.y*sc*w1.y, v1.z*sc*w1.z, v1.w*sc*w1.w);
    float4* op = (float4*)(out + (size_t)t*DM);
    op[lane] = o0; op[lane+32] = o1;
}

// ---------------- BF16 tensor-core GEMM with ldmatrix ----------------
// C[M,N] = A[M,K] @ B[K,N] (+C if RESID). fp32 gmem; bf16 smem; fp32 accum.
// BM=128, BN=64, BK=32, 256 threads (8 warps: 4 M x 2 N), warp tile 32x32.
// A smem: row-major [128][40] bf16 (stride 80B — LDSM conflict-free)
// B smem: row-major [32][72]  bf16 (stride 144B — LDSM conflict-free)
#define ASTR 40
#define BSTR 72

__device__ __forceinline__ void ldsm4(unsigned* r, unsigned addr) {
    asm volatile("ldmatrix.sync.aligned.m8n8.x4.shared.b16 {%0,%1,%2,%3}, [%4];"
        : "=r"(r[0]), "=r"(r[1]), "=r"(r[2]), "=r"(r[3]) : "r"(addr));
}
__device__ __forceinline__ void ldsm4t(unsigned* r, unsigned addr) {
    asm volatile("ldmatrix.sync.aligned.m8n8.x4.trans.shared.b16 {%0,%1,%2,%3}, [%4];"
        : "=r"(r[0]), "=r"(r[1]), "=r"(r[2]), "=r"(r[3]) : "r"(addr));
}

template<bool RESID>
__global__ void __launch_bounds__(256)
gemm_bf16(const float* __restrict__ A, const float* __restrict__ Bm,
          float* __restrict__ C, int M, int N, int K)
{
    __shared__ __align__(16) __nv_bfloat16 As[128*ASTR];
    __shared__ __align__(16) __nv_bfloat16 Bs[32*BSTR];
    const int tid  = threadIdx.x;
    const int m0   = blockIdx.y * 128;
    const int n0   = blockIdx.x * 64;
    const int warp = tid >> 5, lane = tid & 31;
    const int g = lane >> 2, t = lane & 3;
    const int wm = (warp & 3) * 32;
    const int wn = (warp >> 2) * 32;

    // gmem load coords
    const int rowa = tid >> 3, cva = tid & 7;    // A rows rowa+it*32, k=cva*4
    const int rowb = tid >> 4, cvb = tid & 15;   // B rows rowb+it*16, n=cvb*4
    const float* Aptr = A + (size_t)(m0 + rowa)*K + cva*4;
    const float* Bptr = Bm + (size_t)rowb*N + n0 + cvb*4;

    // ldmatrix lane addresses (byte offsets precomputed)
    unsigned aBase = (unsigned)__cvta_generic_to_shared(As);
    unsigned bBase = (unsigned)__cvta_generic_to_shared(Bs);
    unsigned aAddr[2], bAddr[2];
    {
        int arow = (lane & 15);
        int akh  = (lane >> 4) * 8;
        #pragma unroll
        for (int mt = 0; mt < 2; mt++)
            aAddr[mt] = aBase + (unsigned)((wm + mt*16 + arow)*ASTR + akh)*2u;
        int bkr = ((lane >> 3) & 1)*8 + (lane & 7);
        int bnb = (lane >> 4)*8;
        #pragma unroll
        for (int bp = 0; bp < 2; bp++)
            bAddr[bp] = bBase + (unsigned)(bkr*BSTR + wn + bp*16 + bnb)*2u;
    }

    float acc[2][4][4];
    #pragma unroll
    for (int a = 0; a < 2; a++)
        #pragma unroll
        for (int b = 0; b < 4; b++)
            #pragma unroll
            for (int c = 0; c < 4; c++) acc[a][b][c] = 0.f;

    float4 ra[4], rb[2];
    #pragma unroll
    for (int it = 0; it < 4; it++) ra[it] = *(const float4*)(Aptr + (size_t)it*32*K);
    #pragma unroll
    for (int it = 0; it < 2; it++) rb[it] = *(const float4*)(Bptr + (size_t)it*16*N);

    for (int k0 = 0; k0 < K; k0 += 32) {
        // regs -> bf16 smem (vector STS.64)
        #pragma unroll
        for (int it = 0; it < 4; it++) {
            __nv_bfloat162 p0 = __floats2bfloat162_rn(ra[it].x, ra[it].y);
            __nv_bfloat162 p1 = __floats2bfloat162_rn(ra[it].z, ra[it].w);
            uint2 v = make_uint2(*(unsigned*)&p0, *(unsigned*)&p1);
            *(uint2*)&As[(rowa + it*32)*ASTR + cva*4] = v;
        }
        #pragma unroll
        for (int it = 0; it < 2; it++) {
            __nv_bfloat162 p0 = __floats2bfloat162_rn(rb[it].x, rb[it].y);
            __nv_bfloat162 p1 = __floats2bfloat162_rn(rb[it].z, rb[it].w);
            uint2 v = make_uint2(*(unsigned*)&p0, *(unsigned*)&p1);
            *(uint2*)&Bs[(rowb + it*16)*BSTR + cvb*4] = v;
        }
        __syncthreads();

        // prefetch next gmem tile
        if (k0 + 32 < K) {
            #pragma unroll
            for (int it = 0; it < 4; it++)
                ra[it] = *(const float4*)(Aptr + (size_t)it*32*K + k0 + 32);
            #pragma unroll
            for (int it = 0; it < 2; it++)
                rb[it] = *(const float4*)(Bptr + (size_t)(k0 + 32 + it*16)*N);
        }

        // 2 k16-steps: ldmatrix fragments + mma
        #pragma unroll
        for (int ks = 0; ks < 2; ks++) {
            unsigned af[2][4], bq[2][4];
            ldsm4 (af[0], aAddr[0] + ks*32u);          // +16 k-elems * 2B
            ldsm4 (af[1], aAddr[1] + ks*32u);
            ldsm4t(bq[0], bAddr[0] + ks*16u*BSTR*2u);  // +16 k-rows
            ldsm4t(bq[1], bAddr[1] + ks*16u*BSTR*2u);
            #pragma unroll
            for (int mt = 0; mt < 2; mt++)
                #pragma unroll
                for (int nt = 0; nt < 4; nt++) {
                    unsigned b0 = bq[nt>>1][(nt&1)*2];
                    unsigned b1 = bq[nt>>1][(nt&1)*2+1];
                    asm volatile(
                        "mma.sync.aligned.m16n8k16.row.col.f32.bf16.bf16.f32 "
                        "{%0,%1,%2,%3},{%4,%5,%6,%7},{%8,%9},{%0,%1,%2,%3};"
                        : "+f"(acc[mt][nt][0]), "+f"(acc[mt][nt][1]),
                          "+f"(acc[mt][nt][2]), "+f"(acc[mt][nt][3])
                        : "r"(af[mt][0]), "r"(af[mt][1]), "r"(af[mt][2]), "r"(af[mt][3]),
                          "r"(b0), "r"(b1));
                }
        }
        __syncthreads();
    }

    #pragma unroll
    for (int mt = 0; mt < 2; mt++)
        #pragma unroll
        for (int nt = 0; nt < 4; nt++) {
            int row = m0 + wm + mt*16 + g;
            int col = n0 + wn + nt*8 + 2*t;
            float* p0 = C + (size_t)row*N + col;
            float* p1 = C + (size_t)(row+8)*N + col;
            float2 v0 = make_float2(acc[mt][nt][0], acc[mt][nt][1]);
            float2 v1 = make_float2(acc[mt][nt][2], acc[mt][nt][3]);
            if (RESID) {
                float2 c0 = *(const float2*)p0, c1 = *(const float2*)p1;
                v0.x += c0.x; v0.y += c0.y; v1.x += c1.x; v1.y += c1.y;
            }
            *(float2*)p0 = v0;
            *(float2*)p1 = v1;
        }
}

// ---------------- depthwise causal conv(4) + SiLU ----------------
__global__ void conv_silu_kernel(const float* __restrict__ xr, const float* __restrict__ cw,
                                 const float* __restrict__ cb, float* __restrict__ u)
{
    int d  = blockIdx.x * 256 + threadIdx.x;
    int l0 = blockIdx.y * 64;
    int b  = blockIdx.z;
    float4 w   = *(const float4*)(cw + d*4);
    float bias = cb[d];
    const float* xs = xr + ((size_t)b*SEQL)*(2*DI) + d;
    float h0 = (l0 >= 3) ? xs[(size_t)(l0-3)*(2*DI)] : 0.f;
    float h1 = (l0 >= 2) ? xs[(size_t)(l0-2)*(2*DI)] : 0.f;
    float h2 = (l0 >= 1) ? xs[(size_t)(l0-1)*(2*DI)] : 0.f;
    float* up = u + ((size_t)b*SEQL + l0)*DI + d;
    #pragma unroll 4
    for (int i = 0; i < 64; i++) {
        float cur = xs[(size_t)(l0+i)*(2*DI)];
        float z = bias + w.x*h0 + w.y*h1 + w.z*h2 + w.w*cur;
        up[(size_t)i*DI] = z / (1.f + __expf(-z));
        h0 = h1; h1 = h2; h2 = cur;
    }
}

// ---- dt_proj + softplus fused inline ----
__device__ __forceinline__ float dt_softplus(const float4* dtv, const float* w, float bias)
{
    float4 t0 = dtv[0], t1 = dtv[1], t2 = dtv[2], t3 = dtv[3];
    float acc = bias;
    acc += t0.x*w[0]  + t0.y*w[1]  + t0.z*w[2]  + t0.w*w[3];
    acc += t1.x*w[4]  + t1.y*w[5]  + t1.z*w[6]  + t1.w*w[7];
    acc += t2.x*w[8]  + t2.y*w[9]  + t2.z*w[10] + t2.w*w[11];
    acc += t3.x*w[12] + t3.y*w[13] + t3.z*w[14] + t3.w*w[15];
    return softplus_f(acc);
}

// ---------------- chunked scan pass 1: local cumA + local state ----------------
__global__ void __launch_bounds__(128)
scan_pass1(const float* __restrict__ u,  const float* __restrict__ dbc,
           const float* __restrict__ Alog, const float* __restrict__ dtw,
           const float* __restrict__ dtb,
           float* __restrict__ ca, float* __restrict__ cs)
{
    int d = blockIdx.x * 128 + threadIdx.x;
    int c = blockIdx.y;
    int b = blockIdx.z;

    float a2[DS];
    #pragma unroll
    for (int n = 0; n < DS; n++) a2[n] = -__expf(Alog[d*DS + n]) * 1.44269504f;
    bool chain = true;
    #pragma unroll
    for (int n = 1; n < DS; n++)
        if (fabsf(a2[n] - (float)(n+1)*a2[0]) > 1e-4f*fabsf(a2[n])) chain = false;

    float w[DR];
    #pragma unroll
    for (int r = 0; r < DR; r++) w[r] = dtw[r*DI + d];
    float bias = dtb[d];

    float p[DS], s[DS];
    #pragma unroll
    for (int n = 0; n < DS; n++) { p[n] = 1.f; s[n] = 0.f; }

    const float* bc   = dbc + ((size_t)b*SEQL + c*CL)*64;
    const float* uptr = u   + ((size_t)b*SEQL + c*CL)*DI + d;

    if (chain) {
        for (int l = 0; l < CL; l++) {
            const float4* dtv = (const float4*)(bc + (size_t)l*64);
            float dl  = dt_softplus(dtv, w, bias);
            float duv = dl * uptr[(size_t)l*DI];
            const float4* Bv = dtv + 4;
            float e1 = ex2f(dl*a2[0]);
            float e  = e1;
            #pragma unroll
            for (int q = 0; q < 4; q++) {
                float4 Bq = Bv[q];
                p[4*q+0]*=e; s[4*q+0]=e*s[4*q+0]+duv*Bq.x; e*=e1;
                p[4*q+1]*=e; s[4*q+1]=e*s[4*q+1]+duv*Bq.y; e*=e1;
                p[4*q+2]*=e; s[4*q+2]=e*s[4*q+2]+duv*Bq.z; e*=e1;
                p[4*q+3]*=e; s[4*q+3]=e*s[4*q+3]+duv*Bq.w; e*=e1;
            }
        }
    } else {
        for (int l = 0; l < CL; l++) {
            const float4* dtv = (const float4*)(bc + (size_t)l*64);
            float dl  = dt_softplus(dtv, w, bias);
            float duv = dl * uptr[(size_t)l*DI];
            const float4* Bv = dtv + 4;
            #pragma unroll
            for (int q = 0; q < 4; q++) {
                float4 Bq = Bv[q];
                float e;
                e = ex2f(dl*a2[4*q+0]); p[4*q+0]*=e; s[4*q+0]=e*s[4*q+0]+duv*Bq.x;
                e = ex2f(dl*a2[4*q+1]); p[4*q+1]*=e; s[4*q+1]=e*s[4*q+1]+duv*Bq.y;
                e = ex2f(dl*a2[4*q+2]); p[4*q+2]*=e; s[4*q+2]=e*s[4*q+2]+duv*Bq.z;
                e = ex2f(dl*a2[4*q+3]); p[4*q+3]*=e; s[4*q+3]=e*s[4*q+3]+duv*Bq.w;
            }
        }
    }
    size_t o = (((size_t)b*NC + c)*DI + d)*DS;
    #pragma unroll
    for (int q = 0; q < 4; q++) {
        ((float4*)(ca + o))[q] = make_float4(p[4*q], p[4*q+1], p[4*q+2], p[4*q+3]);
        ((float4*)(cs + o))[q] = make_float4(s[4*q], s[4*q+1], s[4*q+2], s[4*q+3]);
    }
}

// ---------------- pass 2: combine chunk transitions -> h0 per chunk ----------------
__global__ void __launch_bounds__(DI)
scan_pass2(const float* __restrict__ ca, const float* __restrict__ cs,
           float* __restrict__ h0)
{
    int b = blockIdx.x, d = threadIdx.x;
    float h[DS];
    #pragma unroll
    for (int n = 0; n < DS; n++) h[n] = 0.f;
    for (int c = 0; c < NC; c++) {
        size_t o = (((size_t)b*NC + c)*DI + d)*DS;
        #pragma unroll
        for (int q = 0; q < 4; q++)
            ((float4*)(h0 + o))[q] = make_float4(h[4*q], h[4*q+1], h[4*q+2], h[4*q+3]);
        #pragma unroll
        for (int q = 0; q < 4; q++) {
            float4 pq = ((const float4*)(ca + o))[q];
            float4 sq = ((const float4*)(cs + o))[q];
            h[4*q+0] = pq.x*h[4*q+0] + sq.x;
            h[4*q+1] = pq.y*h[4*q+1] + sq.y;
            h[4*q+2] = pq.z*h[4*q+2] + sq.z;
            h[4*q+3] = pq.w*h[4*q+3] + sq.w;
        }
    }
}

// ---------------- pass 3: re-scan from h0, emit y = (scan + u*D) * silu(res) ----------------
__global__ void __launch_bounds__(128)
scan_pass3(const float* __restrict__ u,  const float* __restrict__ xr,
           const float* __restrict__ dbc, const float* __restrict__ Alog,
           const float* __restrict__ dtw, const float* __restrict__ dtb,
           const float* __restrict__ Dp,  const float* __restrict__ h0,
           float* __restrict__ y)
{
    int d = blockIdx.x * 128 + threadIdx.x;
    int c = blockIdx.y;
    int b = blockIdx.z;

    float a2[DS];
    #pragma unroll
    for (int n = 0; n < DS; n++) a2[n] = -__expf(Alog[d*DS + n]) * 1.44269504f;
    bool chain = true;
    #pragma unroll
    for (int n = 1; n < DS; n++)
        if (fabsf(a2[n] - (float)(n+1)*a2[0]) > 1e-4f*fabsf(a2[n])) chain = false;

    float w[DR];
    #pragma unroll
    for (int r = 0; r < DR; r++) w[r] = dtw[r*DI + d];
    float bias = dtb[d];
    float Dv = Dp[d];

    float h[DS];
    {
        size_t o = (((size_t)b*NC + c)*DI + d)*DS;
        #pragma unroll
        for (int q = 0; q < 4; q++) {
            float4 hq = ((const float4*)(h0 + o))[q];
            h[4*q] = hq.x; h[4*q+1] = hq.y; h[4*q+2] = hq.z; h[4*q+3] = hq.w;
        }
    }

    const float* bc   = dbc + ((size_t)b*SEQL + c*CL)*64;
    const float* uptr = u   + ((size_t)b*SEQL + c*CL)*DI + d;
    const float* rptr = xr  + ((size_t)b*SEQL + c*CL)*2*DI + DI + d;
    float*       yptr = y   + ((size_t)b*SEQL + c*CL)*DI + d;

    if (chain) {
        for (int l = 0; l < CL; l++) {
            const float4* dtv = (const float4*)(bc + (size_t)l*64);
            float dl  = dt_softplus(dtv, w, bias);
            float uv  = uptr[(size_t)l*DI];
            float duv = dl * uv;
            float res = rptr[(size_t)l*2*DI];
            const float4* Bv = dtv + 4;
            const float4* Cv = dtv + 8;
            float e1 = ex2f(dl*a2[0]);
            float e  = e1;
            float yv = 0.f;
            #pragma unroll
            for (int q = 0; q < 4; q++) {
                float4 Bq = Bv[q], Cq = Cv[q];
                h[4*q+0]=e*h[4*q+0]+duv*Bq.x; yv += h[4*q+0]*Cq.x; e*=e1;
                h[4*q+1]=e*h[4*q+1]+duv*Bq.y; yv += h[4*q+1]*Cq.y; e*=e1;
                h[4*q+2]=e*h[4*q+2]+duv*Bq.z; yv += h[4*q+2]*Cq.z; e*=e1;
                h[4*q+3]=e*h[4*q+3]+duv*Bq.w; yv += h[4*q+3]*Cq.w; e*=e1;
            }
            float o = yv + uv*Dv;
            o *= res / (1.f + __expf(-res));
            yptr[(size_t)l*DI] = o;
        }
    } else {
        for (int l = 0; l < CL; l++) {
            const float4* dtv = (const float4*)(bc + (size_t)l*64);
            float dl  = dt_softplus(dtv, w, bias);
            float uv  = uptr[(size_t)l*DI];
            float duv = dl * uv;
            float res = rptr[(size_t)l*2*DI];
            const float4* Bv = dtv + 4;
            const float4* Cv = dtv + 8;
            float yv = 0.f;
            #pragma unroll
            for (int q = 0; q < 4; q++) {
                float4 Bq = Bv[q], Cq = Cv[q];
                float e;
                e = ex2f(dl*a2[4*q+0]); h[4*q+0]=e*h[4*q+0]+duv*Bq.x; yv += h[4*q+0]*Cq.x;
                e = ex2f(dl*a2[4*q+1]); h[4*q+1]=e*h[4*q+1]+duv*Bq.y; yv += h[4*q+1]*Cq.y;
                e = ex2f(dl*a2[4*q+2]); h[4*q+2]=e*h[4*q+2]+duv*Bq.z; yv += h[4*q+2]*Cq.z;
                e = ex2f(dl*a2[4*q+3]); h[4*q+3]=e*h[4*q+3]+duv*Bq.w; yv += h[4*q+3]*Cq.w;
            }
            float o = yv + uv*Dv;
            o *= res / (1.f + __expf(-res));
            yptr[(size_t)l*DI] = o;
        }
    }
}

// ---------------- pad x_proj_w (L,512,48) -> (L,512,64) zero-padded ----------------
__global__ void pad_xpw_kernel(const float* __restrict__ xpw, float* __restrict__ out)
{
    int idx = blockIdx.x * 256 + threadIdx.x;
    int j  = idx & 63;
    int rk = idx >> 6;
    out[idx] = (j < 48) ? xpw[rk*48 + j] : 0.f;
}

// ---------------- deterministic two-stage mean over L ----------------
__global__ void mean_part_kernel(const float* __restrict__ seq, float* __restrict__ part)
{
    int b = blockIdx.x, c = blockIdx.y, e = threadIdx.x;
    const float* p = seq + ((size_t)b*SEQL + c*64)*DM + e;
    float s = 0.f;
    #pragma unroll 8
    for (int i = 0; i < 64; i++) s += p[(size_t)i*DM];
    part[(b*16 + c)*DM + e] = s;
}
__global__ void mean_final_kernel(const float* __restrict__ part, float* __restrict__ out)
{
    int b = blockIdx.x, e = threadIdx.x;
    float s = 0.f;
    #pragma unroll
    for (int c = 0; c < 16; c++) s += part[(b*16 + c)*DM + e];
    out[b*DM + e] = s * (1.f/1024.f);
}

// ---------------- launch ----------------
extern "C" void kernel_launch(void* const* d_in, const int* in_sizes, int n_in,
                              void* d_out, int out_size)
{
    const float* x    = (const float*)d_in[0];
    const float* plg  = (const float*)d_in[1];
    const float* plb  = (const float*)d_in[2];
    const float* ew   = (const float*)d_in[3];
    const float* eb   = (const float*)d_in[4];
    const float* elg  = (const float*)d_in[5];
    const float* elb  = (const float*)d_in[6];
    const float* rmsw = (const float*)d_in[7];
    const float* inw  = (const float*)d_in[8];
    const float* cw   = (const float*)d_in[9];
    const float* cb   = (const float*)d_in[10];
    const float* xpw  = (const float*)d_in[11];
    const float* dtw  = (const float*)d_in[12];
    const float* dtb  = (const float*)d_in[13];
    const float* Alog = (const float*)d_in[14];
    const float* Dpar = (const float*)d_in[15];
    const float* ow   = (const float*)d_in[16];

    float *seq, *xn, *xr, *u, *dbc, *y, *xpwp, *part, *ca, *cs, *h0;
    cudaGetSymbolAddress((void**)&seq,   g_seq);
    cudaGetSymbolAddress((void**)&xn,    g_xn);
    cudaGetSymbolAddress((void**)&xr,    g_xr);
    cudaGetSymbolAddress((void**)&u,     g_u);
    cudaGetSymbolAddress((void**)&dbc,   g_dbc);
    cudaGetSymbolAddress((void**)&y,     g_y);
    cudaGetSymbolAddress((void**)&xpwp,  g_xpw);
    cudaGetSymbolAddress((void**)&part,  g_part);
    cudaGetSymbolAddress((void**)&ca,    g_ca);
    cudaGetSymbolAddress((void**)&cs,    g_cs);
    cudaGetSymbolAddress((void**)&h0,    g_h0);

    const int M = BATCH * SEQL;  // 16384

    pad_xpw_kernel<<<512, 256>>>(xpw, xpwp);
    patch_embed_kernel<<<2048, 256>>>(x, plg, plb, ew, eb, elg, elb, seq);

    for (int L = 0; L < NL; L++) {
        rmsnorm_kernel<<<2048, 256>>>(seq, rmsw + L*DM, xn);

        // in_proj: (16384,256) @ (256,1024) — bf16 tensor cores
        gemm_bf16<false><<<dim3(16, 128), 256>>>(
            xn, inw + (size_t)L*DM*2*DI, xr, M, 2*DI, DM);

        conv_silu_kernel<<<dim3(2,16,16), 256>>>(xr, cw + L*DI*4, cb + L*DI, u);

        // x_proj: (16384,512) @ (512,64pad) — bf16 tensor cores
        gemm_bf16<false><<<dim3(1, 128), 256>>>(
            u, xpwp + (size_t)L*DI*64, dbc, M, 64, DI);

        scan_pass1<<<dim3(4, NC, BATCH), 128>>>(u, dbc, Alog + L*DI*DS,
                                                dtw + L*DR*DI, dtb + L*DI, ca, cs);
        scan_pass2<<<BATCH, DI>>>(ca, cs, h0);
        scan_pass3<<<dim3(4, NC, BATCH), 128>>>(u, xr, dbc, Alog + L*DI*DS,
                                                dtw + L*DR*DI, dtb + L*DI,
                                                Dpar + L*DI, h0, y);

        // out_proj (+residual into seq): (16384,512) @ (512,256) — bf16 tensor cores
        gemm_bf16<true><<<dim3(4, 128), 256>>>(
            y, ow + (size_t)L*DI*DM, seq, M, DM, DI);
    }

    mean_part_kernel<<<dim3(16,16), 256>>>(seq, part);
    mean_final_kernel<<<16, 256>>>(part, (float*)d_out);
}

// round 6
// speedup vs baseline: 6.1459x; 1.0742x over previous
#include <cuda_runtime.h>
#include <cuda_bf16.h>
#include <math.h>

#define BATCH 16
#define SEQL  1024
#define DM    256
#define DI    512
#define DS    16
#define DR    16
#define NL    4
#define NC    16        // scan chunks
#define CL    (SEQL/NC) // 64 steps per chunk

typedef unsigned long long ull;

// ---------------- scratch (static device globals; no allocation) ----------------
__device__ float g_seq  [BATCH*SEQL*DM];
__device__ __nv_bfloat16 g_xnb [BATCH*SEQL*DM];
__device__ float g_xr   [BATCH*SEQL*2*DI];
__device__ float g_u    [BATCH*SEQL*DI];
__device__ __nv_bfloat16 g_ub  [BATCH*SEQL*DI];
__device__ float g_dbc  [BATCH*SEQL*64];
__device__ __nv_bfloat16 g_yb  [BATCH*SEQL*DI];
__device__ __nv_bfloat16 g_inwb[NL*DM*2*DI];
__device__ __nv_bfloat16 g_owb [NL*DI*DM];
__device__ __nv_bfloat16 g_xpwb[NL*DI*64];
__device__ float g_part [BATCH*16*DM];
__device__ float g_ca   [BATCH*NC*DI*DS];
__device__ float g_cs   [BATCH*NC*DI*DS];
__device__ float g_h0   [BATCH*NC*DI*DS];

__device__ __forceinline__ float ex2f(float x) {
    float r; asm("ex2.approx.f32 %0, %1;" : "=f"(r) : "f"(x)); return r;
}
__device__ __forceinline__ float lg2f(float x) {
    float r; asm("lg2.approx.f32 %0, %1;" : "=f"(r) : "f"(x)); return r;
}
__device__ __forceinline__ float softplus_f(float x) {
    float t = ex2f(x * 1.44269504f);
    return (x > 15.f) ? x : 0.69314718f * lg2f(1.f + t);
}
// ---- packed f32x2 helpers (sm_100+) ----
__device__ __forceinline__ ull pk2(float lo, float hi) {
    ull r; asm("mov.b64 %0, {%1,%2};" : "=l"(r) : "f"(lo), "f"(hi)); return r;
}
__device__ __forceinline__ void upk2(ull v, float& lo, float& hi) {
    asm("mov.b64 {%0,%1}, %2;" : "=f"(lo), "=f"(hi) : "l"(v));
}
__device__ __forceinline__ ull mul2(ull a, ull b) {
    ull r; asm("mul.rn.f32x2 %0, %1, %2;" : "=l"(r) : "l"(a), "l"(b)); return r;
}
__device__ __forceinline__ ull fma2(ull a, ull b, ull c) {
    ull r; asm("fma.rn.f32x2 %0, %1, %2, %3;" : "=l"(r) : "l"(a), "l"(b), "l"(c)); return r;
}

// ---------------- fp32 -> bf16 bulk convert ----------------
__global__ void f2b_kernel(const float* __restrict__ src, __nv_bfloat16* __restrict__ dst, int n)
{
    int i = (blockIdx.x * 256 + threadIdx.x) * 4;
    if (i < n) {
        float4 v = *(const float4*)(src + i);
        __nv_bfloat162 p0 = __floats2bfloat162_rn(v.x, v.y);
        __nv_bfloat162 p1 = __floats2bfloat162_rn(v.z, v.w);
        *(uint2*)(dst + i) = make_uint2(*(unsigned*)&p0, *(unsigned*)&p1);
    }
}

// ---------------- pad x_proj_w (L,512,48) -> (L,512,64) bf16 zero-padded ----------------
__global__ void pad_xpw_kernel(const float* __restrict__ xpw, __nv_bfloat16* __restrict__ out)
{
    int idx = blockIdx.x * 256 + threadIdx.x;  // NL*DI*64
    int j  = idx & 63;
    int rk = idx >> 6;
    out[idx] = __float2bfloat16((j < 48) ? xpw[rk*48 + j] : 0.f);
}

// ---------------- patch extract + LN(48) + embed(48->256) + LN(256) ----------------
__global__ void patch_embed_kernel(const float* __restrict__ x,
                                   const float* __restrict__ plg, const float* __restrict__ plb,
                                   const float* __restrict__ ew,  const float* __restrict__ eb,
                                   const float* __restrict__ elg, const float* __restrict__ elb,
                                   float* __restrict__ seq)
{
    __shared__ float sp[8][48];
    int warp = threadIdx.x >> 5, lane = threadIdx.x & 31;
    int t = blockIdx.x * 8 + warp;
    int b = t >> 10, pos = t & 1023;
    int hy = pos >> 5, wx = pos & 31;

    float p1, p2 = 0.f;
    {
        int j = lane;
        int c = j >> 4, py = (j >> 2) & 3, px = j & 3;
        p1 = x[((b*3 + c)*128 + hy*4 + py)*128 + wx*4 + px];
        if (lane < 16) {
            j = 32 + lane;
            c = j >> 4; py = (j >> 2) & 3; px = j & 3;
            p2 = x[((b*3 + c)*128 + hy*4 + py)*128 + wx*4 + px];
        }
    }
    float s = p1 + p2, ss = p1*p1 + p2*p2;
    #pragma unroll
    for (int o = 16; o > 0; o >>= 1) {
        s  += __shfl_xor_sync(0xffffffffu, s,  o);
        ss += __shfl_xor_sync(0xffffffffu, ss, o);
    }
    float mu  = s * (1.f/48.f);
    float var = ss * (1.f/48.f) - mu*mu;
    float rs  = rsqrtf(var + 1e-5f);
    sp[warp][lane] = (p1 - mu)*rs*plg[lane] + plb[lane];
    if (lane < 16) sp[warp][32+lane] = (p2 - mu)*rs*plg[32+lane] + plb[32+lane];
    __syncwarp();

    float acc[8];
    #pragma unroll
    for (int i = 0; i < 8; i++) acc[i] = eb[lane + 32*i];
    #pragma unroll 4
    for (int j = 0; j < 48; j++) {
        float v = sp[warp][j];
        const float* w = ew + j*DM + lane;
        #pragma unroll
        for (int i = 0; i < 8; i++) acc[i] += v * w[32*i];
    }
    float s2 = 0.f, ss2 = 0.f;
    #pragma unroll
    for (int i = 0; i < 8; i++) { s2 += acc[i]; ss2 += acc[i]*acc[i]; }
    #pragma unroll
    for (int o = 16; o > 0; o >>= 1) {
        s2  += __shfl_xor_sync(0xffffffffu, s2,  o);
        ss2 += __shfl_xor_sync(0xffffffffu, ss2, o);
    }
    float mu2  = s2 * (1.f/256.f);
    float var2 = ss2 * (1.f/256.f) - mu2*mu2;
    float rs2  = rsqrtf(var2 + 1e-5f);
    #pragma unroll
    for (int i = 0; i < 8; i++) {
        int e = lane + 32*i;
        seq[(size_t)t*DM + e] = (acc[i] - mu2)*rs2*elg[e] + elb[e];
    }
}

// ---------------- rmsnorm over DM=256, bf16 output ----------------
__global__ void rmsnorm_kernel(const float* __restrict__ in, const float* __restrict__ w,
                               __nv_bfloat16* __restrict__ out)
{
    int warp = threadIdx.x >> 5, lane = threadIdx.x & 31;
    int t = blockIdx.x * 8 + warp;
    const float4* ip = (const float4*)(in + (size_t)t*DM);
    float4 v0 = ip[lane], v1 = ip[lane+32];
    float ss = v0.x*v0.x+v0.y*v0.y+v0.z*v0.z+v0.w*v0.w
             + v1.x*v1.x+v1.y*v1.y+v1.z*v1.z+v1.w*v1.w;
    #pragma unroll
    for (int o = 16; o > 0; o >>= 1) ss += __shfl_xor_sync(0xffffffffu, ss, o);
    float sc = rsqrtf(ss*(1.f/256.f) + 1e-5f);
    const float4* wp = (const float4*)w;
    float4 w0 = wp[lane], w1 = wp[lane+32];
    __nv_bfloat162 a0 = __floats2bfloat162_rn(v0.x*sc*w0.x, v0.y*sc*w0.y);
    __nv_bfloat162 a1 = __floats2bfloat162_rn(v0.z*sc*w0.z, v0.w*sc*w0.w);
    __nv_bfloat162 b0 = __floats2bfloat162_rn(v1.x*sc*w1.x, v1.y*sc*w1.y);
    __nv_bfloat162 b1 = __floats2bfloat162_rn(v1.z*sc*w1.z, v1.w*sc*w1.w);
    __nv_bfloat16* op = out + (size_t)t*DM;
    *(uint2*)(op + lane*4)      = make_uint2(*(unsigned*)&a0, *(unsigned*)&a1);
    *(uint2*)(op + (lane+32)*4) = make_uint2(*(unsigned*)&b0, *(unsigned*)&b1);
}

// ---------------- BF16-in BF16-smem tensor-core GEMM with ldmatrix ----------------
// C[M,N](fp32) = A[M,K](bf16) @ B[K,N](bf16) (+C if RESID)
// BM=128, BN=64, BK=32, 256 threads (8 warps: 4 M x 2 N), warp tile 32x32.
#define ASTR 40
#define BSTR 72

__device__ __forceinline__ void ldsm4(unsigned* r, unsigned addr) {
    asm volatile("ldmatrix.sync.aligned.m8n8.x4.shared.b16 {%0,%1,%2,%3}, [%4];"
        : "=r"(r[0]), "=r"(r[1]), "=r"(r[2]), "=r"(r[3]) : "r"(addr));
}
__device__ __forceinline__ void ldsm4t(unsigned* r, unsigned addr) {
    asm volatile("ldmatrix.sync.aligned.m8n8.x4.trans.shared.b16 {%0,%1,%2,%3}, [%4];"
        : "=r"(r[0]), "=r"(r[1]), "=r"(r[2]), "=r"(r[3]) : "r"(addr));
}

template<bool RESID>
__global__ void __launch_bounds__(256)
gemm_bf16(const __nv_bfloat16* __restrict__ A, const __nv_bfloat16* __restrict__ Bm,
          float* __restrict__ C, int M, int N, int K)
{
    __shared__ __align__(16) __nv_bfloat16 As[128*ASTR];
    __shared__ __align__(16) __nv_bfloat16 Bs[32*BSTR];
    const int tid  = threadIdx.x;
    const int m0   = blockIdx.y * 128;
    const int n0   = blockIdx.x * 64;
    const int warp = tid >> 5, lane = tid & 31;
    const int g = lane >> 2, t = lane & 3;
    const int wm = (warp & 3) * 32;
    const int wn = (warp >> 2) * 32;

    // gmem load coords (bf16, 8 elems per LDG.128)
    const int rowa = tid >> 2, ca = tid & 3;     // A rows rowa, rowa+64; k = ca*8
    const int rowb = tid >> 3, cb = tid & 7;     // B row rowb; n = cb*8
    const __nv_bfloat16* Ap = A + (size_t)(m0 + rowa)*K + ca*8;
    const __nv_bfloat16* Bp = Bm + (size_t)rowb*N + n0 + cb*8;

    // ldmatrix lane addresses
    unsigned aBase = (unsigned)__cvta_generic_to_shared(As);
    unsigned bBase = (unsigned)__cvta_generic_to_shared(Bs);
    unsigned aAddr[2], bAddr[2];
    {
        int arow = (lane & 15);
        int akh  = (lane >> 4) * 8;
        #pragma unroll
        for (int mt = 0; mt < 2; mt++)
            aAddr[mt] = aBase + (unsigned)((wm + mt*16 + arow)*ASTR + akh)*2u;
        int bkr = ((lane >> 3) & 1)*8 + (lane & 7);
        int bnb = (lane >> 4)*8;
        #pragma unroll
        for (int bp = 0; bp < 2; bp++)
            bAddr[bp] = bBase + (unsigned)(bkr*BSTR + wn + bp*16 + bnb)*2u;
    }

    float acc[2][4][4];
    #pragma unroll
    for (int a = 0; a < 2; a++)
        #pragma unroll
        for (int b = 0; b < 4; b++)
            #pragma unroll
            for (int c = 0; c < 4; c++) acc[a][b][c] = 0.f;

    uint4 ra[2], rb;
    ra[0] = *(const uint4*)Ap;
    ra[1] = *(const uint4*)(Ap + (size_t)64*K);
    rb    = *(const uint4*)Bp;

    for (int k0 = 0; k0 < K; k0 += 32) {
        *(uint4*)&As[rowa*ASTR + ca*8]        = ra[0];
        *(uint4*)&As[(rowa + 64)*ASTR + ca*8] = ra[1];
        *(uint4*)&Bs[rowb*BSTR + cb*8]        = rb;
        __syncthreads();

        if (k0 + 32 < K) {
            ra[0] = *(const uint4*)(Ap + k0 + 32);
            ra[1] = *(const uint4*)(Ap + (size_t)64*K + k0 + 32);
            rb    = *(const uint4*)(Bp + (size_t)(k0 + 32)*N);
        }

        #pragma unroll
        for (int ks = 0; ks < 2; ks++) {
            unsigned af[2][4], bq[2][4];
            ldsm4 (af[0], aAddr[0] + ks*32u);
            ldsm4 (af[1], aAddr[1] + ks*32u);
            ldsm4t(bq[0], bAddr[0] + ks*16u*BSTR*2u);
            ldsm4t(bq[1], bAddr[1] + ks*16u*BSTR*2u);
            #pragma unroll
            for (int mt = 0; mt < 2; mt++)
                #pragma unroll
                for (int nt = 0; nt < 4; nt++) {
                    unsigned b0 = bq[nt>>1][(nt&1)*2];
                    unsigned b1 = bq[nt>>1][(nt&1)*2+1];
                    asm volatile(
                        "mma.sync.aligned.m16n8k16.row.col.f32.bf16.bf16.f32 "
                        "{%0,%1,%2,%3},{%4,%5,%6,%7},{%8,%9},{%0,%1,%2,%3};"
                        : "+f"(acc[mt][nt][0]), "+f"(acc[mt][nt][1]),
                          "+f"(acc[mt][nt][2]), "+f"(acc[mt][nt][3])
                        : "r"(af[mt][0]), "r"(af[mt][1]), "r"(af[mt][2]), "r"(af[mt][3]),
                          "r"(b0), "r"(b1));
                }
        }
        __syncthreads();
    }

    #pragma unroll
    for (int mt = 0; mt < 2; mt++)
        #pragma unroll
        for (int nt = 0; nt < 4; nt++) {
            int row = m0 + wm + mt*16 + g;
            int col = n0 + wn + nt*8 + 2*t;
            float* p0 = C + (size_t)row*N + col;
            float* p1 = C + (size_t)(row+8)*N + col;
            float2 v0 = make_float2(acc[mt][nt][0], acc[mt][nt][1]);
            float2 v1 = make_float2(acc[mt][nt][2], acc[mt][nt][3]);
            if (RESID) {
                float2 c0 = *(const float2*)p0, c1 = *(const float2*)p1;
                v0.x += c0.x; v0.y += c0.y; v1.x += c1.x; v1.y += c1.y;
            }
            *(float2*)p0 = v0;
            *(float2*)p1 = v1;
        }
}

// ---------------- depthwise causal conv(4) + SiLU (fp32 + bf16 outputs) ----------------
__global__ void conv_silu_kernel(const float* __restrict__ xr, const float* __restrict__ cw,
                                 const float* __restrict__ cb, float* __restrict__ u,
                                 __nv_bfloat16* __restrict__ ub)
{
    int d  = blockIdx.x * 256 + threadIdx.x;
    int l0 = blockIdx.y * 64;
    int b  = blockIdx.z;
    float4 w   = *(const float4*)(cw + d*4);
    float bias = cb[d];
    const float* xs = xr + ((size_t)b*SEQL)*(2*DI) + d;
    float h0 = (l0 >= 3) ? xs[(size_t)(l0-3)*(2*DI)] : 0.f;
    float h1 = (l0 >= 2) ? xs[(size_t)(l0-2)*(2*DI)] : 0.f;
    float h2 = (l0 >= 1) ? xs[(size_t)(l0-1)*(2*DI)] : 0.f;
    float* up = u + ((size_t)b*SEQL + l0)*DI + d;
    __nv_bfloat16* ubp = ub + ((size_t)b*SEQL + l0)*DI + d;
    #pragma unroll 4
    for (int i = 0; i < 64; i++) {
        float cur = xs[(size_t)(l0+i)*(2*DI)];
        float z = bias + w.x*h0 + w.y*h1 + w.z*h2 + w.w*cur;
        float sv = z / (1.f + __expf(-z));
        up[(size_t)i*DI]  = sv;
        ubp[(size_t)i*DI] = __float2bfloat16(sv);
        h0 = h1; h1 = h2; h2 = cur;
    }
}

// ---- dt_proj + softplus fused inline ----
__device__ __forceinline__ float dt_softplus(const float4* dtv, const float* w, float bias)
{
    float4 t0 = dtv[0], t1 = dtv[1], t2 = dtv[2], t3 = dtv[3];
    float acc = bias;
    acc += t0.x*w[0]  + t0.y*w[1]  + t0.z*w[2]  + t0.w*w[3];
    acc += t1.x*w[4]  + t1.y*w[5]  + t1.z*w[6]  + t1.w*w[7];
    acc += t2.x*w[8]  + t2.y*w[9]  + t2.z*w[10] + t2.w*w[11];
    acc += t3.x*w[12] + t3.y*w[13] + t3.z*w[14] + t3.w*w[15];
    return softplus_f(acc);
}

// ---------------- chunked scan pass 1: local cumA + local state ----------------
__global__ void __launch_bounds__(128)
scan_pass1(const float* __restrict__ u,  const float* __restrict__ dbc,
           const float* __restrict__ Alog, const float* __restrict__ dtw,
           const float* __restrict__ dtb,
           float* __restrict__ ca, float* __restrict__ cs)
{
    int d = blockIdx.x * 128 + threadIdx.x;
    int c = blockIdx.y;
    int b = blockIdx.z;

    float a2[DS];
    #pragma unroll
    for (int n = 0; n < DS; n++) a2[n] = -__expf(Alog[d*DS + n]) * 1.44269504f;
    bool chain = true;
    #pragma unroll
    for (int n = 1; n < DS; n++)
        if (fabsf(a2[n] - (float)(n+1)*a2[0]) > 1e-4f*fabsf(a2[n])) chain = false;

    float w[DR];
    #pragma unroll
    for (int r = 0; r < DR; r++) w[r] = dtw[r*DI + d];
    float bias = dtb[d];

    const float* bc   = dbc + ((size_t)b*SEQL + c*CL)*64;
    const float* uptr = u   + ((size_t)b*SEQL + c*CL)*DI + d;
    size_t o = (((size_t)b*NC + c)*DI + d)*DS;

    if (chain) {
        ull p2[8], s2[8];
        #pragma unroll
        for (int q = 0; q < 8; q++) { p2[q] = pk2(1.f, 1.f); s2[q] = 0ull; }
        float a20 = a2[0];
        for (int l = 0; l < CL; l++) {
            const float4* dtv = (const float4*)(bc + (size_t)l*64);
            float dl  = dt_softplus(dtv, w, bias);
            float duv = dl * uptr[(size_t)l*DI];
            float e1  = ex2f(dl*a20);
            float e1s = e1*e1;
            ull ep   = pk2(e1, e1s);
            ull es2  = pk2(e1s, e1s);
            ull duv2 = pk2(duv, duv);
            const ulonglong2* B4 = (const ulonglong2*)(bc + (size_t)l*64 + 16);
            #pragma unroll
            for (int j = 0; j < 4; j++) {
                ulonglong2 Bp = B4[j];
                ull db0 = mul2(Bp.x, duv2);
                s2[2*j]   = fma2(ep, s2[2*j],   db0);
                p2[2*j]   = mul2(p2[2*j], ep);
                ep = mul2(ep, es2);
                ull db1 = mul2(Bp.y, duv2);
                s2[2*j+1] = fma2(ep, s2[2*j+1], db1);
                p2[2*j+1] = mul2(p2[2*j+1], ep);
                if (j < 3) ep = mul2(ep, es2);
            }
        }
        #pragma unroll
        for (int q = 0; q < 8; q++) {
            ((ull*)(ca + o))[q] = p2[q];
            ((ull*)(cs + o))[q] = s2[q];
        }
    } else {
        float p[DS], s[DS];
        #pragma unroll
        for (int n = 0; n < DS; n++) { p[n] = 1.f; s[n] = 0.f; }
        for (int l = 0; l < CL; l++) {
            const float4* dtv = (const float4*)(bc + (size_t)l*64);
            float dl  = dt_softplus(dtv, w, bias);
            float duv = dl * uptr[(size_t)l*DI];
            const float4* Bv = dtv + 4;
            #pragma unroll
            for (int q = 0; q < 4; q++) {
                float4 Bq = Bv[q];
                float e;
                e = ex2f(dl*a2[4*q+0]); p[4*q+0]*=e; s[4*q+0]=e*s[4*q+0]+duv*Bq.x;
                e = ex2f(dl*a2[4*q+1]); p[4*q+1]*=e; s[4*q+1]=e*s[4*q+1]+duv*Bq.y;
                e = ex2f(dl*a2[4*q+2]); p[4*q+2]*=e; s[4*q+2]=e*s[4*q+2]+duv*Bq.z;
                e = ex2f(dl*a2[4*q+3]); p[4*q+3]*=e; s[4*q+3]=e*s[4*q+3]+duv*Bq.w;
            }
        }
        #pragma unroll
        for (int q = 0; q < 4; q++) {
            ((float4*)(ca + o))[q] = make_float4(p[4*q], p[4*q+1], p[4*q+2], p[4*q+3]);
            ((float4*)(cs + o))[q] = make_float4(s[4*q], s[4*q+1], s[4*q+2], s[4*q+3]);
        }
    }
}

// ---------------- pass 2: combine chunk transitions -> h0 per chunk ----------------
__global__ void __launch_bounds__(DI)
scan_pass2(const float* __restrict__ ca, const float* __restrict__ cs,
           float* __restrict__ h0)
{
    int b = blockIdx.x, d = threadIdx.x;
    float h[DS];
    #pragma unroll
    for (int n = 0; n < DS; n++) h[n] = 0.f;
    for (int c = 0; c < NC; c++) {
        size_t o = (((size_t)b*NC + c)*DI + d)*DS;
        #pragma unroll
        for (int q = 0; q < 4; q++)
            ((float4*)(h0 + o))[q] = make_float4(h[4*q], h[4*q+1], h[4*q+2], h[4*q+3]);
        #pragma unroll
        for (int q = 0; q < 4; q++) {
            float4 pq = ((const float4*)(ca + o))[q];
            float4 sq = ((const float4*)(cs + o))[q];
            h[4*q+0] = pq.x*h[4*q+0] + sq.x;
            h[4*q+1] = pq.y*h[4*q+1] + sq.y;
            h[4*q+2] = pq.z*h[4*q+2] + sq.z;
            h[4*q+3] = pq.w*h[4*q+3] + sq.w;
        }
    }
}

// ---------------- pass 3: re-scan from h0, emit y(bf16) = (scan + u*D) * silu(res) ----------------
__global__ void __launch_bounds__(128)
scan_pass3(const float* __restrict__ u,  const float* __restrict__ xr,
           const float* __restrict__ dbc, const float* __restrict__ Alog,
           const float* __restrict__ dtw, const float* __restrict__ dtb,
           const float* __restrict__ Dp,  const float* __restrict__ h0,
           __nv_bfloat16* __restrict__ y)
{
    int d = blockIdx.x * 128 + threadIdx.x;
    int c = blockIdx.y;
    int b = blockIdx.z;

    float a2[DS];
    #pragma unroll
    for (int n = 0; n < DS; n++) a2[n] = -__expf(Alog[d*DS + n]) * 1.44269504f;
    bool chain = true;
    #pragma unroll
    for (int n = 1; n < DS; n++)
        if (fabsf(a2[n] - (float)(n+1)*a2[0]) > 1e-4f*fabsf(a2[n])) chain = false;

    float w[DR];
    #pragma unroll
    for (int r = 0; r < DR; r++) w[r] = dtw[r*DI + d];
    float bias = dtb[d];
    float Dv = Dp[d];

    const float* bc   = dbc + ((size_t)b*SEQL + c*CL)*64;
    const float* uptr = u   + ((size_t)b*SEQL + c*CL)*DI + d;
    const float* rptr = xr  + ((size_t)b*SEQL + c*CL)*2*DI + DI + d;
    __nv_bfloat16* yptr = y + ((size_t)b*SEQL + c*CL)*DI + d;
    size_t o0 = (((size_t)b*NC + c)*DI + d)*DS;

    if (chain) {
        ull h2[8];
        #pragma unroll
        for (int q = 0; q < 8; q++) h2[q] = ((const ull*)(h0 + o0))[q];
        float a20 = a2[0];
        for (int l = 0; l < CL; l++) {
            const float4* dtv = (const float4*)(bc + (size_t)l*64);
            float dl  = dt_softplus(dtv, w, bias);
            float uv  = uptr[(size_t)l*DI];
            float duv = dl * uv;
            float res = rptr[(size_t)l*2*DI];
            float e1  = ex2f(dl*a20);
            float e1s = e1*e1;
            ull ep   = pk2(e1, e1s);
            ull es2  = pk2(e1s, e1s);
            ull duv2 = pk2(duv, duv);
            const ulonglong2* B4 = (const ulonglong2*)(bc + (size_t)l*64 + 16);
            const ulonglong2* C4 = (const ulonglong2*)(bc + (size_t)l*64 + 32);
            ull y2 = 0ull;
            #pragma unroll
            for (int j = 0; j < 4; j++) {
                ulonglong2 Bp = B4[j], Cp = C4[j];
                ull db0 = mul2(Bp.x, duv2);
                h2[2*j] = fma2(ep, h2[2*j], db0);
                y2 = fma2(h2[2*j], Cp.x, y2);
                ep = mul2(ep, es2);
                ull db1 = mul2(Bp.y, duv2);
                h2[2*j+1] = fma2(ep, h2[2*j+1], db1);
                y2 = fma2(h2[2*j+1], Cp.y, y2);
                if (j < 3) ep = mul2(ep, es2);
            }
            float ylo, yhi; upk2(y2, ylo, yhi);
            float ov = ylo + yhi + uv*Dv;
            ov *= res / (1.f + __expf(-res));
            yptr[(size_t)l*DI] = __float2bfloat16(ov);
        }
    } else {
        float h[DS];
        #pragma unroll
        for (int q = 0; q < 4; q++) {
            float4 hq = ((const float4*)(h0 + o0))[q];
            h[4*q] = hq.x; h[4*q+1] = hq.y; h[4*q+2] = hq.z; h[4*q+3] = hq.w;
        }
        for (int l = 0; l < CL; l++) {
            const float4* dtv = (const float4*)(bc + (size_t)l*64);
            float dl  = dt_softplus(dtv, w, bias);
            float uv  = uptr[(size_t)l*DI];
            float duv = dl * uv;
            float res = rptr[(size_t)l*2*DI];
            const float4* Bv = dtv + 4;
            const float4* Cv = dtv + 8;
            float yv = 0.f;
            #pragma unroll
            for (int q = 0; q < 4; q++) {
                float4 Bq = Bv[q], Cq = Cv[q];
                float e;
                e = ex2f(dl*a2[4*q+0]); h[4*q+0]=e*h[4*q+0]+duv*Bq.x; yv += h[4*q+0]*Cq.x;
                e = ex2f(dl*a2[4*q+1]); h[4*q+1]=e*h[4*q+1]+duv*Bq.y; yv += h[4*q+1]*Cq.y;
                e = ex2f(dl*a2[4*q+2]); h[4*q+2]=e*h[4*q+2]+duv*Bq.z; yv += h[4*q+2]*Cq.z;
                e = ex2f(dl*a2[4*q+3]); h[4*q+3]=e*h[4*q+3]+duv*Bq.w; yv += h[4*q+3]*Cq.w;
            }
            float ov = yv + uv*Dv;
            ov *= res / (1.f + __expf(-res));
            yptr[(size_t)l*DI] = __float2bfloat16(ov);
        }
    }
}

// ---------------- deterministic two-stage mean over L ----------------
__global__ void mean_part_kernel(const float* __restrict__ seq, float* __restrict__ part)
{
    int b = blockIdx.x, c = blockIdx.y, e = threadIdx.x;
    const float* p = seq + ((size_t)b*SEQL + c*64)*DM + e;
    float s = 0.f;
    #pragma unroll 8
    for (int i = 0; i < 64; i++) s += p[(size_t)i*DM];
    part[(b*16 + c)*DM + e] = s;
}
__global__ void mean_final_kernel(const float* __restrict__ part, float* __restrict__ out)
{
    int b = blockIdx.x, e = threadIdx.x;
    float s = 0.f;
    #pragma unroll
    for (int c = 0; c < 16; c++) s += part[(b*16 + c)*DM + e];
    out[b*DM + e] = s * (1.f/1024.f);
}

// ---------------- launch ----------------
extern "C" void kernel_launch(void* const* d_in, const int* in_sizes, int n_in,
                              void* d_out, int out_size)
{
    const float* x    = (const float*)d_in[0];
    const float* plg  = (const float*)d_in[1];
    const float* plb  = (const float*)d_in[2];
    const float* ew   = (const float*)d_in[3];
    const float* eb   = (const float*)d_in[4];
    const float* elg  = (const float*)d_in[5];
    const float* elb  = (const float*)d_in[6];
    const float* rmsw = (const float*)d_in[7];
    const float* inw  = (const float*)d_in[8];
    const float* cw   = (const float*)d_in[9];
    const float* cb   = (const float*)d_in[10];
    const float* xpw  = (const float*)d_in[11];
    const float* dtw  = (const float*)d_in[12];
    const float* dtb  = (const float*)d_in[13];
    const float* Alog = (const float*)d_in[14];
    const float* Dpar = (const float*)d_in[15];
    const float* ow   = (const float*)d_in[16];

    float *seq, *xr, *u, *dbc, *part, *ca, *cs, *h0;
    __nv_bfloat16 *xnb, *ub, *yb, *inwb, *owb, *xpwb;
    cudaGetSymbolAddress((void**)&seq,   g_seq);
    cudaGetSymbolAddress((void**)&xnb,   g_xnb);
    cudaGetSymbolAddress((void**)&xr,    g_xr);
    cudaGetSymbolAddress((void**)&u,     g_u);
    cudaGetSymbolAddress((void**)&ub,    g_ub);
    cudaGetSymbolAddress((void**)&dbc,   g_dbc);
    cudaGetSymbolAddress((void**)&yb,    g_yb);
    cudaGetSymbolAddress((void**)&inwb,  g_inwb);
    cudaGetSymbolAddress((void**)&owb,   g_owb);
    cudaGetSymbolAddress((void**)&xpwb,  g_xpwb);
    cudaGetSymbolAddress((void**)&part,  g_part);
    cudaGetSymbolAddress((void**)&ca,    g_ca);
    cudaGetSymbolAddress((void**)&cs,    g_cs);
    cudaGetSymbolAddress((void**)&h0,    g_h0);

    const int M = BATCH * SEQL;  // 16384

    // one-time weight conversion (runs per launch; deterministic)
    f2b_kernel<<<(NL*DM*2*DI/4 + 255)/256, 256>>>(inw, inwb, NL*DM*2*DI);
    f2b_kernel<<<(NL*DI*DM/4 + 255)/256, 256>>>(ow, owb, NL*DI*DM);
    pad_xpw_kernel<<<NL*DI*64/256, 256>>>(xpw, xpwb);
    patch_embed_kernel<<<2048, 256>>>(x, plg, plb, ew, eb, elg, elb, seq);

    for (int L = 0; L < NL; L++) {
        rmsnorm_kernel<<<2048, 256>>>(seq, rmsw + L*DM, xnb);

        // in_proj: (16384,256) @ (256,1024)
        gemm_bf16<false><<<dim3(16, 128), 256>>>(
            xnb, inwb + (size_t)L*DM*2*DI, xr, M, 2*DI, DM);

        conv_silu_kernel<<<dim3(2,16,16), 256>>>(xr, cw + L*DI*4, cb + L*DI, u, ub);

        // x_proj: (16384,512) @ (512,64pad)
        gemm_bf16<false><<<dim3(1, 128), 256>>>(
            ub, xpwb + (size_t)L*DI*64, dbc, M, 64, DI);

        scan_pass1<<<dim3(4, NC, BATCH), 128>>>(u, dbc, Alog + L*DI*DS,
                                                dtw + L*DR*DI, dtb + L*DI, ca, cs);
        scan_pass2<<<BATCH, DI>>>(ca, cs, h0);
        scan_pass3<<<dim3(4, NC, BATCH), 128>>>(u, xr, dbc, Alog + L*DI*DS,
                                                dtw + L*DR*DI, dtb + L*DI,
                                                Dpar + L*DI, h0, yb);

        // out_proj (+residual into seq): (16384,512) @ (512,256)
        gemm_bf16<true><<<dim3(4, 128), 256>>>(
            yb, owb + (size_t)L*DI*DM, seq, M, DM, DI);
    }

    mean_part_kernel<<<dim3(16,16), 256>>>(seq, part);
    mean_final_kernel<<<16, 256>>>(part, (float*)d_out);
}